// round 14
// baseline (speedup 1.0000x reference)
#include <cuda_runtime.h>
#include <cuda_fp16.h>
#include <cstdint>

// Problem constants
#define CB   2048
#define CT   64
#define CM   256
#define CP   256
#define G    28      // batches per block
#define NBLK 74      // ceil(2048/28)
#define GPAD 30      // sGate row stride (floats)
#define DSS  520     // sDSh row stride in halves ([d(256) | c(256)] + pad)

// decoder smem layout (float offsets)
#define OFF_SGATE 0        // [1024][GPAD] fp32 gates      = 30720
#define OFF_SDSH  30720    // [32][DSS] fp16 [d|c]         = 8320 floats
#define OFF_SX1H  39040    // [28][256] fp16 x1            = 3584 floats
#define OFF_SCT   42624    // [28][256] fp32 context       = 7168
#define OFF_SL    49792    // [28][64] scores/beta         = 1792
#define OFF_SYT   51584    // [32] y_tilda
#define SMEM_FLOATS 51616
#define SMEM_BYTES  (SMEM_FLOATS * 4)   // 206,464 B

// ue_tc smem: [128][280] halves
#define UE_STRIDE 280
#define UE_SMEM_BYTES (128 * UE_STRIDE * 2)

typedef unsigned long long ull;

// ---------------- device scratch ----------------
__device__ __align__(16) __half  g_UeH[(size_t)CB * CT * CM];   // fp16 Ue
__device__ __align__(16) float   g_we[(size_t)CB * CT];         // enc . w_tilda
__device__ __align__(16) uint4   g_WdF[16 * 32 * 32];           // Wd  fragments [w][kt][lane]
__device__ __align__(16) uint4   g_WhhF[16 * 16 * 4 * 32];      // Whh fragments [w][kt][mt][lane]
__device__ __align__(16) uint2   g_UdF2[32 * 16 * 32];          // Ud  B-fragments [nt][kt][lane]
__device__ float g_bcomb[1024];
__device__ float g_weff[512];
__device__ float g_beff[1];

// ---------------- helpers ----------------
__device__ __forceinline__ ull pack2(float lo, float hi) {
    ull r; asm("mov.b64 %0, {%1, %2};" : "=l"(r) : "f"(lo), "f"(hi)); return r;
}
__device__ __forceinline__ ull bcast2(float x) { return pack2(x, x); }
__device__ __forceinline__ ull fma2(ull a, ull b, ull c) {
    ull d; asm("fma.rn.f32x2 %0, %1, %2, %3;" : "=l"(d) : "l"(a), "l"(b), "l"(c)); return d;
}
__device__ __forceinline__ float2 unpack2(ull v) {
    float2 f; asm("mov.b64 {%0, %1}, %2;" : "=f"(f.x), "=f"(f.y) : "l"(v)); return f;
}
__device__ __forceinline__ float fast_ex2(float x) {
    float y; asm("ex2.approx.f32 %0, %1;" : "=f"(y) : "f"(x)); return y;
}
__device__ __forceinline__ float fast_rcp(float x) {
    float y; asm("rcp.approx.f32 %0, %1;" : "=f"(y) : "f"(x)); return y;
}
__device__ __forceinline__ float tanh_f(float x) {
    float e = fast_ex2(2.8853900817779268f * x);
    return fmaf(-2.f, fast_rcp(e + 1.f), 1.f);
}
__device__ __forceinline__ unsigned tanh_h2(unsigned x) {
    unsigned y; asm("tanh.approx.f16x2 %0, %1;" : "=r"(y) : "r"(x)); return y;
}
__device__ __forceinline__ float sigm_f(float x) {
    float e = fast_ex2(-1.4426950408889634f * x);
    return fast_rcp(1.f + e);
}
__device__ __forceinline__ float wredsum(float s) {
#pragma unroll
    for (int o = 16; o; o >>= 1) s += __shfl_xor_sync(0xffffffffu, s, o);
    return s;
}
__device__ __forceinline__ float wredmax(float s) {
#pragma unroll
    for (int o = 16; o; o >>= 1) s = fmaxf(s, __shfl_xor_sync(0xffffffffu, s, o));
    return s;
}
// m16n8k16 row.col f32.f16.f16.f32
__device__ __forceinline__ void mma16816(float* c, uint4 A, uint32_t b0, uint32_t b1) {
    asm volatile("mma.sync.aligned.m16n8k16.row.col.f32.f16.f16.f32 "
        "{%0,%1,%2,%3}, {%4,%5,%6,%7}, {%8,%9}, {%0,%1,%2,%3};"
        : "+f"(c[0]), "+f"(c[1]), "+f"(c[2]), "+f"(c[3])
        : "r"(A.x), "r"(A.y), "r"(A.z), "r"(A.w), "r"(b0), "r"(b1));
}

// ---------------- prep: weight fragments + folded head ----------------
__global__ void prep_kernel(const float* __restrict__ Wd,
                            const float* __restrict__ Whh,
                            const float* __restrict__ Ud,
                            const float* __restrict__ bih,
                            const float* __restrict__ bhh,
                            const float* __restrict__ vy,
                            const float* __restrict__ Wy,
                            const float* __restrict__ Wyb,
                            const float* __restrict__ vyb)
{
    int i = blockIdx.x * blockDim.x + threadIdx.x;
    if (i < 16384) {   // Wd fragments: [w(16)][kt(32)][lane(32)]
        int lane = i & 31, kt = (i >> 5) & 31, w = i >> 10;
        int j0 = w * 16 + (lane >> 2);
        int k0 = kt * 16 + (lane & 3) * 2;
        __half2 a = __floats2half2_rn(Wd[j0 * 512 + k0],       Wd[j0 * 512 + k0 + 1]);
        __half2 b = __floats2half2_rn(Wd[(j0 + 8) * 512 + k0], Wd[(j0 + 8) * 512 + k0 + 1]);
        __half2 c = __floats2half2_rn(Wd[j0 * 512 + k0 + 8],   Wd[j0 * 512 + k0 + 9]);
        __half2 d = __floats2half2_rn(Wd[(j0 + 8) * 512 + k0 + 8], Wd[(j0 + 8) * 512 + k0 + 9]);
        uint4 v;
        v.x = *(uint32_t*)&a; v.y = *(uint32_t*)&b; v.z = *(uint32_t*)&c; v.w = *(uint32_t*)&d;
        g_WdF[i] = v;
        return;
    }
    i -= 16384;
    if (i < 32768) {   // Whh fragments: [w(16)][kt(16)][mt(4)][lane(32)]
        int lane = i & 31, mt = (i >> 5) & 3, kt = (i >> 7) & 15, w = i >> 11;
        int j0 = w * 64 + mt * 16 + (lane >> 2);
        int k0 = kt * 16 + (lane & 3) * 2;
        __half2 a = __floats2half2_rn(Whh[j0 * 256 + k0],       Whh[j0 * 256 + k0 + 1]);
        __half2 b = __floats2half2_rn(Whh[(j0 + 8) * 256 + k0], Whh[(j0 + 8) * 256 + k0 + 1]);
        __half2 c = __floats2half2_rn(Whh[j0 * 256 + k0 + 8],   Whh[j0 * 256 + k0 + 9]);
        __half2 d = __floats2half2_rn(Whh[(j0 + 8) * 256 + k0 + 8], Whh[(j0 + 8) * 256 + k0 + 9]);
        uint4 v;
        v.x = *(uint32_t*)&a; v.y = *(uint32_t*)&b; v.z = *(uint32_t*)&c; v.w = *(uint32_t*)&d;
        g_WhhF[i] = v;
        return;
    }
    i -= 32768;
    if (i < 16384) {   // Ud B-fragments: [nt(32)][kt(16)][lane(32)]
        int lane = i & 31, kt = (i >> 5) & 15, nt = i >> 9;
        int n = nt * 8 + (lane >> 2);
        int k0 = kt * 16 + (lane & 3) * 2;
        __half2 b0 = __floats2half2_rn(Ud[n * 256 + k0],     Ud[n * 256 + k0 + 1]);
        __half2 b1 = __floats2half2_rn(Ud[n * 256 + k0 + 8], Ud[n * 256 + k0 + 9]);
        uint2 v; v.x = *(uint32_t*)&b0; v.y = *(uint32_t*)&b1;
        g_UdF2[i] = v;
        return;
    }
    i -= 16384;
    if (i < 1024) { g_bcomb[i] = bih[i] + bhh[i]; return; }
    i -= 1024;
    if (i < 512) {
        float s = 0.f;
        for (int j = 0; j < 256; ++j) s += vy[j] * Wy[j * 512 + i];
        g_weff[i] = s; return;
    }
    i -= 512;
    if (i == 0) {
        float s = 0.f;
        for (int j = 0; j < 256; ++j) s += vy[j] * Wyb[j];
        g_beff[0] = s + vyb[0];
    }
}

// ---------------- ue_tc: Ue = enc @ Ud^T via HMMA; we = enc.wt ----------------
__global__ __launch_bounds__(256, 2) void ue_tc_kernel(const float* __restrict__ enc,
                                                       const float* __restrict__ wt)
{
    extern __shared__ __align__(16) __half Eh[];
    const int tid  = threadIdx.x;
    const int lane = tid & 31;
    const int w    = tid >> 5;
    const int bt0  = blockIdx.x * 128;

    for (int i = tid; i < 8192; i += 256) {
        int r = i >> 6, c4 = i & 63;
        float4 v = ((const float4*)(enc + (size_t)(bt0 + r) * 256))[c4];
        __half2 h0 = __floats2half2_rn(v.x, v.y);
        __half2 h1 = __floats2half2_rn(v.z, v.w);
        *(__half2*)&Eh[r * UE_STRIDE + c4 * 4]     = h0;
        *(__half2*)&Eh[r * UE_STRIDE + c4 * 4 + 2] = h1;
    }
    __syncthreads();

    {
        float2 wtr[4];
#pragma unroll
        for (int i = 0; i < 4; ++i)
            wtr[i] = make_float2(wt[i * 64 + lane * 2], wt[i * 64 + lane * 2 + 1]);
        for (int r = w; r < 128; r += 8) {
            float s = 0.f;
#pragma unroll
            for (int i = 0; i < 4; ++i) {
                float2 f = __half22float2(*(__half2*)&Eh[r * UE_STRIDE + i * 64 + lane * 2]);
                s = fmaf(f.x, wtr[i].x, fmaf(f.y, wtr[i].y, s));
            }
            s = wredsum(s);
            if (lane == 0) g_we[bt0 + r] = s;
        }
    }

    const int r0   = w * 16 + (lane >> 2);
    const int koff = (lane & 3) * 2;
    const int cc   = (lane & 3) * 2;
#pragma unroll
    for (int pass = 0; pass < 2; ++pass) {
        float acc[16][4];
#pragma unroll
        for (int nt = 0; nt < 16; ++nt)
#pragma unroll
            for (int q = 0; q < 4; ++q) acc[nt][q] = 0.f;

        for (int kt = 0; kt < 16; ++kt) {
            uint4 A;
            A.x = *(const uint32_t*)&Eh[r0 * UE_STRIDE + kt * 16 + koff];
            A.y = *(const uint32_t*)&Eh[(r0 + 8) * UE_STRIDE + kt * 16 + koff];
            A.z = *(const uint32_t*)&Eh[r0 * UE_STRIDE + kt * 16 + koff + 8];
            A.w = *(const uint32_t*)&Eh[(r0 + 8) * UE_STRIDE + kt * 16 + koff + 8];
#pragma unroll
            for (int nt = 0; nt < 16; ++nt) {
                uint2 B = g_UdF2[((((pass * 16 + nt) << 4) + kt) << 5) + lane];
                mma16816(acc[nt], A, B.x, B.y);
            }
        }
#pragma unroll
        for (int nt = 0; nt < 16; ++nt) {
            int ncol = ((pass * 16 + nt) << 3) + cc;
            __half2 h01 = __floats2half2_rn(acc[nt][0], acc[nt][1]);
            __half2 h23 = __floats2half2_rn(acc[nt][2], acc[nt][3]);
            *(__half2*)(g_UeH + (size_t)(bt0 + r0) * 256 + ncol)     = h01;
            *(__half2*)(g_UeH + (size_t)(bt0 + r0 + 8) * 256 + ncol) = h23;
        }
    }
}

// ---------------- persistent decoder: 74 blocks x 512 thr, G=28 ----------------
__global__ __launch_bounds__(512, 1) void decoder_kernel(
    const float* __restrict__ enc,
    const float* __restrict__ yin,
    const float* __restrict__ Wdb, const float* __restrict__ vd,
    const float* __restrict__ wt,  const float* __restrict__ wtb,
    const float* __restrict__ Wih, float* __restrict__ out)
{
    extern __shared__ __align__(16) float sm[];
    float*  sGate = sm + OFF_SGATE;            // [1024][GPAD]
    __half* sDSh  = (__half*)(sm + OFF_SDSH);  // [32][DSS]
    __half* sX1h  = (__half*)(sm + OFF_SX1H);  // [28][256]
    float*  sCt   = sm + OFF_SCT;              // [28][256]
    float*  sL    = sm + OFF_SL;               // [28][64]
    float*  sYt   = sm + OFF_SYT;              // [32]

    const int tid  = threadIdx.x;
    const int lane = tid & 31;
    const int wid  = tid >> 5;
    const int half = tid >> 8;
    const int n    = tid & 255;
    const int base = blockIdx.x * G;

    // zero fp16 state buffer (32 rows incl pad) + sYt
    for (int i = tid; i < 8320; i += 512) ((float*)sDSh)[i] = 0.f;
    if (tid < 32) sYt[tid] = 0.f;

    ull vd2[4];
#pragma unroll
    for (int j = 0; j < 4; ++j)
        vd2[j] = pack2(vd[lane * 8 + 2 * j], vd[lane * 8 + 2 * j + 1]);
    const float wt256 = wt[256];
    const float wtb0  = wtb[0];

    // pointwise constants (unit n) + cell state in registers (14 batches each)
    const float bI = g_bcomb[n],       wI = Wih[n];
    const float bF = g_bcomb[256 + n], wF = Wih[256 + n];
    const float bG = g_bcomb[512 + n], wG = Wih[512 + n];
    const float bO = g_bcomb[768 + n], wO = Wih[768 + n];
    float creg[14];
#pragma unroll
    for (int j = 0; j < 14; ++j) creg[j] = 0.f;

    // MMA geometry
    const int qrow = lane >> 2;
    const int koff = (lane & 3) * 2;
    const int r0A  = wid * 16 + qrow;
    const float bbA0 = Wdb[r0A], bbA1 = Wdb[r0A + 8];
    const uint4* afA = g_WdF  + (wid << 10) + lane;
    const uint4* afE = g_WhhF + (wid << 11) + lane;

    __syncthreads();

    for (int t = 0; t < CT; ++t) {
        // ---- MMA-A: x1[256x28] = Wd[256x512] @ [d;c][512x28] : 4 N-tiles per A-frag ----
        {
            float cA[4][4];
#pragma unroll
            for (int nt = 0; nt < 4; ++nt)
#pragma unroll
                for (int q = 0; q < 4; ++q) cA[nt][q] = 0.f;
#pragma unroll 4
            for (int kt = 0; kt < 32; ++kt) {
                uint4 A = afA[kt << 5];
                int k0 = (kt << 4) + koff;
#pragma unroll
                for (int nt = 0; nt < 4; ++nt) {
                    int gc = nt * 8 + qrow;
                    uint32_t b0 = *(const uint32_t*)(sDSh + gc * DSS + k0);
                    uint32_t b1 = *(const uint32_t*)(sDSh + gc * DSS + k0 + 8);
                    mma16816(cA[nt], A, b0, b1);
                }
            }
#pragma unroll
            for (int nt = 0; nt < 4; ++nt) {
                int g0 = nt * 8 + (lane & 3) * 2;
                if (g0 < G) {   // g0 even => g0+1 <= 27 too
                    sX1h[g0 * 256 + r0A]           = __float2half_rn(cA[nt][0] + bbA0);
                    sX1h[g0 * 256 + r0A + 8]       = __float2half_rn(cA[nt][2] + bbA1);
                    sX1h[(g0 + 1) * 256 + r0A]     = __float2half_rn(cA[nt][1] + bbA0);
                    sX1h[(g0 + 1) * 256 + r0A + 8] = __float2half_rn(cA[nt][3] + bbA1);
                }
            }
        }
        __syncthreads();

        // ---- Phase B: attention scores, 28 batches (no barrier into MMA-E) ----
        for (int p0 = wid; p0 < G * CT; p0 += 64) {
            uint4 u[4];
#pragma unroll
            for (int j = 0; j < 4; ++j) {
                int p = p0 + 16 * j;
                int b = min(base + (p >> 6), CB - 1);
                u[j] = *((const uint4*)(g_UeH + (((size_t)b * CT + (p & 63)) << 8)) + lane);
            }
            float sres[4];
#pragma unroll
            for (int j = 0; j < 4; ++j) {
                int p = p0 + 16 * j;
                uint4 x = *((const uint4*)(sX1h + ((p >> 6) << 8)) + lane);
                const __half2* uh = (const __half2*)&u[j];
                const __half2* xh = (const __half2*)&x;
                __half2 s0 = __hadd2(uh[0], xh[0]);
                __half2 s1 = __hadd2(uh[1], xh[1]);
                __half2 s2 = __hadd2(uh[2], xh[2]);
                __half2 s3 = __hadd2(uh[3], xh[3]);
                unsigned z0 = tanh_h2(*(unsigned*)&s0);
                unsigned z1 = tanh_h2(*(unsigned*)&s1);
                unsigned z2 = tanh_h2(*(unsigned*)&s2);
                unsigned z3 = tanh_h2(*(unsigned*)&s3);
                float2 f0 = __half22float2(*(__half2*)&z0);
                float2 f1 = __half22float2(*(__half2*)&z1);
                float2 f2 = __half22float2(*(__half2*)&z2);
                float2 f3 = __half22float2(*(__half2*)&z3);
                ull acc = 0ull;
                acc = fma2(pack2(f0.x, f0.y), vd2[0], acc);
                acc = fma2(pack2(f1.x, f1.y), vd2[1], acc);
                acc = fma2(pack2(f2.x, f2.y), vd2[2], acc);
                acc = fma2(pack2(f3.x, f3.y), vd2[3], acc);
                float2 f = unpack2(acc);
                sres[j] = f.x + f.y;
            }
#pragma unroll
            for (int o = 16; o; o >>= 1) {
#pragma unroll
                for (int j = 0; j < 4; ++j)
                    sres[j] += __shfl_xor_sync(0xffffffffu, sres[j], o);
            }
            if (lane == 0) {
#pragma unroll
                for (int j = 0; j < 4; ++j) sL[p0 + 16 * j] = sres[j];
            }
        }

        // ---- MMA-E: gates[1024x28], 2 mt-passes, each Whh frag read once ----
#pragma unroll
        for (int pass = 0; pass < 2; ++pass) {
            float cE[2][4][4];
#pragma unroll
            for (int m = 0; m < 2; ++m)
#pragma unroll
                for (int nt = 0; nt < 4; ++nt)
#pragma unroll
                    for (int q = 0; q < 4; ++q) cE[m][nt][q] = 0.f;
#pragma unroll 2
            for (int kt = 0; kt < 16; ++kt) {
                int k0 = (kt << 4) + koff;
                uint32_t b0[4], b1[4];
#pragma unroll
                for (int nt = 0; nt < 4; ++nt) {
                    int gc = nt * 8 + qrow;
                    b0[nt] = *(const uint32_t*)(sDSh + gc * DSS + k0);
                    b1[nt] = *(const uint32_t*)(sDSh + gc * DSS + k0 + 8);
                }
                uint4 A0 = afE[((kt << 2) + 2 * pass) << 5];
                uint4 A1 = afE[((kt << 2) + 2 * pass + 1) << 5];
#pragma unroll
                for (int nt = 0; nt < 4; ++nt) {
                    mma16816(cE[0][nt], A0, b0[nt], b1[nt]);
                    mma16816(cE[1][nt], A1, b0[nt], b1[nt]);
                }
            }
#pragma unroll
            for (int m = 0; m < 2; ++m) {
                int row = wid * 64 + (2 * pass + m) * 16 + qrow;
#pragma unroll
                for (int nt = 0; nt < 4; ++nt) {
                    int g0 = nt * 8 + (lane & 3) * 2;
                    if (g0 < G) {   // FIX: guard pad columns (28,30) -> no row overflow
                        *(float2*)&sGate[row * GPAD + g0]       = make_float2(cE[m][nt][0], cE[m][nt][1]);
                        *(float2*)&sGate[(row + 8) * GPAD + g0] = make_float2(cE[m][nt][2], cE[m][nt][3]);
                    }
                }
            }
        }
        __syncthreads();

        // ---- B2: softmax + fused y_tilda (warps cover 28 batches) ----
        for (int gl = wid; gl < G; gl += 16) {
            int b = min(base + gl, CB - 1);
            float l0 = sL[gl * 64 + lane], l1 = sL[gl * 64 + 32 + lane];
            float mx = wredmax(fmaxf(l0, l1));
            float e0 = fast_ex2((l0 - mx) * 1.4426950408889634f);
            float e1 = fast_ex2((l1 - mx) * 1.4426950408889634f);
            float w0 = g_we[b * CT + lane], w1 = g_we[b * CT + 32 + lane];
            float ps = e0 + e1;
            float pw = fmaf(e0, w0, e1 * w1);
#pragma unroll
            for (int o = 16; o; o >>= 1) {
                ps += __shfl_xor_sync(0xffffffffu, ps, o);
                pw += __shfl_xor_sync(0xffffffffu, pw, o);
            }
            float inv = fast_rcp(ps);
            inv = inv * (2.f - ps * inv);
            sL[gl * 64 + lane]      = e0 * inv;
            sL[gl * 64 + 32 + lane] = e1 * inv;
            if (lane == 0) {
                float yt = yin[b * CT + t];
                sYt[gl] = fmaf(pw, inv, fmaf(yt, wt256, wtb0));
            }
        }
        __syncthreads();

        // ---- Pointwise: unit n, 14 batches per thread, cell state in regs ----
        {
#pragma unroll
            for (int j = 0; j < 14; ++j) {
                int g = half * 14 + j;
                float yt = sYt[g];
                float iv = sGate[n * GPAD + g]         + bI + yt * wI;
                float fv = sGate[(256 + n) * GPAD + g] + bF + yt * wF;
                float gv = sGate[(512 + n) * GPAD + g] + bG + yt * wG;
                float ov = sGate[(768 + n) * GPAD + g] + bO + yt * wO;
                float cn = fmaf(sigm_f(fv), creg[j], sigm_f(iv) * tanh_f(gv));
                creg[j] = cn;
                float h = sigm_f(ov) * tanh_f(cn);
                sDSh[g * DSS + n]       = __float2half_rn(h);
                sDSh[g * DSS + 256 + n] = __float2half_rn(cn);
            }
        }
        __syncthreads();
    }

    // ---- Phase C (once): c_t = beta @ enc (fp32, 28 batches) ----
    for (int gl = wid; gl < G; gl += 16) {
        int b = min(base + gl, CB - 1);
        const float4* ep = (const float4*)(enc + (size_t)b * CT * 256) + lane * 2;
        float4 a0 = make_float4(0.f, 0.f, 0.f, 0.f);
        float4 a1 = make_float4(0.f, 0.f, 0.f, 0.f);
#pragma unroll 4
        for (int tt = 0; tt < 64; ++tt) {
            float bb = sL[gl * 64 + tt];
            float4 e0 = ep[tt * 64];
            float4 e1 = ep[tt * 64 + 1];
            a0.x = fmaf(bb, e0.x, a0.x); a0.y = fmaf(bb, e0.y, a0.y);
            a0.z = fmaf(bb, e0.z, a0.z); a0.w = fmaf(bb, e0.w, a0.w);
            a1.x = fmaf(bb, e1.x, a1.x); a1.y = fmaf(bb, e1.y, a1.y);
            a1.z = fmaf(bb, e1.z, a1.z); a1.w = fmaf(bb, e1.w, a1.w);
        }
        float* cp = sCt + gl * 256 + lane * 8;
        ((float4*)cp)[0] = a0;
        ((float4*)cp)[1] = a1;
    }
    __syncthreads();

    // ---- Final head ----
    for (int gl = wid; gl < G; gl += 16) {
        float s = 0.f;
#pragma unroll
        for (int i = 0; i < 8; ++i) {
            int m = lane + 32 * i;
            s = fmaf(__half2float(sDSh[gl * DSS + m]), g_weff[m], s);
            s = fmaf(sCt[gl * 256 + m], g_weff[256 + m], s);
        }
        s = wredsum(s);
        if (lane == 0 && base + gl < CB) out[base + gl] = s + g_beff[0];
    }
    for (int p = tid; p < G * CT; p += 512) {
        int gl = p >> 6, tt = p & 63;
        if (base + gl < CB)
            out[CB + (size_t)(base + gl) * CT + tt] = sL[gl * 64 + tt];
    }
}

// ---------------- launcher ----------------
extern "C" void kernel_launch(void* const* d_in, const int* in_sizes, int n_in,
                              void* d_out, int out_size)
{
    (void)in_sizes; (void)n_in; (void)out_size;
    const float* enc = (const float*)d_in[0];
    const float* y   = (const float*)d_in[1];
    const float* Wd  = (const float*)d_in[2];
    const float* Wdb = (const float*)d_in[3];
    const float* Ud  = (const float*)d_in[4];
    const float* vd  = (const float*)d_in[5];
    const float* wt  = (const float*)d_in[6];
    const float* wtb = (const float*)d_in[7];
    const float* Wy  = (const float*)d_in[8];
    const float* Wyb = (const float*)d_in[9];
    const float* vy  = (const float*)d_in[10];
    const float* vyb = (const float*)d_in[11];
    const float* Wih = (const float*)d_in[12];
    const float* Whh = (const float*)d_in[13];
    const float* bih = (const float*)d_in[14];
    const float* bhh = (const float*)d_in[15];
    float* out = (float*)d_out;

    cudaFuncSetAttribute(decoder_kernel,
                         cudaFuncAttributeMaxDynamicSharedMemorySize, SMEM_BYTES);
    cudaFuncSetAttribute(ue_tc_kernel,
                         cudaFuncAttributeMaxDynamicSharedMemorySize, UE_SMEM_BYTES);

    prep_kernel<<<263, 256>>>(Wd, Whh, Ud, bih, bhh, vy, Wy, Wyb, vyb);
    ue_tc_kernel<<<1024, 256, UE_SMEM_BYTES>>>(enc, wt);
    decoder_kernel<<<NBLK, 512, SMEM_BYTES>>>(enc, y, Wdb, vd, wt, wtb, Wih, out);
}

// round 15
// speedup vs baseline: 1.7233x; 1.7233x over previous
#include <cuda_runtime.h>
#include <cuda_fp16.h>
#include <cstdint>

// Problem constants
#define CB   2048
#define CT   64
#define CM   256
#define CP   256
#define G    14      // batches per block
#define NBLK 147
#define DSS  520     // sDSh row stride in halves ([d(256) | c(256)] + pad)

// decoder smem layout (float offsets)
#define OFF_SDSH  0        // [16][DSS] fp16 [d|c]   = 4160 floats
#define OFF_SX1H  4160     // [16][256] fp16 x1      = 2048 floats
#define OFF_SCT   6208     // [14][256] fp32 context = 3584
#define OFF_SL    9792     // [14][64] scores/beta   = 896
#define OFF_SYT   10688    // [16] y_tilda
#define SMEM_FLOATS 10704
#define SMEM_BYTES  (SMEM_FLOATS * 4)   // 42,816 B

// ue_tc smem: [128][280] halves
#define UE_STRIDE 280
#define UE_SMEM_BYTES (128 * UE_STRIDE * 2)

typedef unsigned long long ull;

// ---------------- device scratch ----------------
__device__ __align__(16) __half  g_UeH[(size_t)CB * CT * CM];   // fp16 Ue
__device__ __align__(16) float   g_we[(size_t)CB * CT];         // enc . w_tilda
__device__ __align__(16) uint4   g_WdF[16 * 32 * 32];           // Wd  fragments [w][kt][lane]
__device__ __align__(16) uint4   g_WhhF[16 * 16 * 4 * 32];      // Whh fragments [w][kt][mt][lane]
__device__ __align__(16) uint2   g_UdF2[32 * 16 * 32];          // Ud  B-fragments [nt][kt][lane]
__device__ float g_bcomb[1024];
__device__ float g_weff[512];
__device__ float g_beff[1];

// ---------------- helpers ----------------
__device__ __forceinline__ ull pack2(float lo, float hi) {
    ull r; asm("mov.b64 %0, {%1, %2};" : "=l"(r) : "f"(lo), "f"(hi)); return r;
}
__device__ __forceinline__ ull bcast2(float x) { return pack2(x, x); }
__device__ __forceinline__ ull fma2(ull a, ull b, ull c) {
    ull d; asm("fma.rn.f32x2 %0, %1, %2, %3;" : "=l"(d) : "l"(a), "l"(b), "l"(c)); return d;
}
__device__ __forceinline__ float2 unpack2(ull v) {
    float2 f; asm("mov.b64 {%0, %1}, %2;" : "=f"(f.x), "=f"(f.y) : "l"(v)); return f;
}
__device__ __forceinline__ float fast_ex2(float x) {
    float y; asm("ex2.approx.f32 %0, %1;" : "=f"(y) : "f"(x)); return y;
}
__device__ __forceinline__ float fast_rcp(float x) {
    float y; asm("rcp.approx.f32 %0, %1;" : "=f"(y) : "f"(x)); return y;
}
__device__ __forceinline__ float tanh_f(float x) {
    float e = fast_ex2(2.8853900817779268f * x);
    return fmaf(-2.f, fast_rcp(e + 1.f), 1.f);
}
__device__ __forceinline__ unsigned tanh_h2(unsigned x) {
    unsigned y; asm("tanh.approx.f16x2 %0, %1;" : "=r"(y) : "r"(x)); return y;
}
__device__ __forceinline__ float sigm_f(float x) {
    float e = fast_ex2(-1.4426950408889634f * x);
    return fast_rcp(1.f + e);
}
__device__ __forceinline__ float wredsum(float s) {
#pragma unroll
    for (int o = 16; o; o >>= 1) s += __shfl_xor_sync(0xffffffffu, s, o);
    return s;
}
__device__ __forceinline__ float wredmax(float s) {
#pragma unroll
    for (int o = 16; o; o >>= 1) s = fmaxf(s, __shfl_xor_sync(0xffffffffu, s, o));
    return s;
}
// m16n8k16 row.col f32.f16.f16.f32
__device__ __forceinline__ void mma16816(float* c, uint4 A, uint32_t b0, uint32_t b1) {
    asm volatile("mma.sync.aligned.m16n8k16.row.col.f32.f16.f16.f32 "
        "{%0,%1,%2,%3}, {%4,%5,%6,%7}, {%8,%9}, {%0,%1,%2,%3};"
        : "+f"(c[0]), "+f"(c[1]), "+f"(c[2]), "+f"(c[3])
        : "r"(A.x), "r"(A.y), "r"(A.z), "r"(A.w), "r"(b0), "r"(b1));
}

// ---------------- prep: weight fragments + folded head (identical to R9) ----------------
__global__ void prep_kernel(const float* __restrict__ Wd,
                            const float* __restrict__ Whh,
                            const float* __restrict__ Ud,
                            const float* __restrict__ bih,
                            const float* __restrict__ bhh,
                            const float* __restrict__ vy,
                            const float* __restrict__ Wy,
                            const float* __restrict__ Wyb,
                            const float* __restrict__ vyb)
{
    int i = blockIdx.x * blockDim.x + threadIdx.x;
    if (i < 16384) {   // Wd fragments: [w(16)][kt(32)][lane(32)]
        int lane = i & 31, kt = (i >> 5) & 31, w = i >> 10;
        int j0 = w * 16 + (lane >> 2);
        int k0 = kt * 16 + (lane & 3) * 2;
        __half2 a = __floats2half2_rn(Wd[j0 * 512 + k0],       Wd[j0 * 512 + k0 + 1]);
        __half2 b = __floats2half2_rn(Wd[(j0 + 8) * 512 + k0], Wd[(j0 + 8) * 512 + k0 + 1]);
        __half2 c = __floats2half2_rn(Wd[j0 * 512 + k0 + 8],   Wd[j0 * 512 + k0 + 9]);
        __half2 d = __floats2half2_rn(Wd[(j0 + 8) * 512 + k0 + 8], Wd[(j0 + 8) * 512 + k0 + 9]);
        uint4 v;
        v.x = *(uint32_t*)&a; v.y = *(uint32_t*)&b; v.z = *(uint32_t*)&c; v.w = *(uint32_t*)&d;
        g_WdF[i] = v;
        return;
    }
    i -= 16384;
    if (i < 32768) {   // Whh fragments: [w(16)][kt(16)][mt(4)][lane(32)]  (tile T = w*4+mt, rows T*16..+16)
        int lane = i & 31, mt = (i >> 5) & 3, kt = (i >> 7) & 15, w = i >> 11;
        int j0 = w * 64 + mt * 16 + (lane >> 2);
        int k0 = kt * 16 + (lane & 3) * 2;
        __half2 a = __floats2half2_rn(Whh[j0 * 256 + k0],       Whh[j0 * 256 + k0 + 1]);
        __half2 b = __floats2half2_rn(Whh[(j0 + 8) * 256 + k0], Whh[(j0 + 8) * 256 + k0 + 1]);
        __half2 c = __floats2half2_rn(Whh[j0 * 256 + k0 + 8],   Whh[j0 * 256 + k0 + 9]);
        __half2 d = __floats2half2_rn(Whh[(j0 + 8) * 256 + k0 + 8], Whh[(j0 + 8) * 256 + k0 + 9]);
        uint4 v;
        v.x = *(uint32_t*)&a; v.y = *(uint32_t*)&b; v.z = *(uint32_t*)&c; v.w = *(uint32_t*)&d;
        g_WhhF[i] = v;
        return;
    }
    i -= 32768;
    if (i < 16384) {   // Ud B-fragments: [nt(32)][kt(16)][lane(32)]
        int lane = i & 31, kt = (i >> 5) & 15, nt = i >> 9;
        int n = nt * 8 + (lane >> 2);
        int k0 = kt * 16 + (lane & 3) * 2;
        __half2 b0 = __floats2half2_rn(Ud[n * 256 + k0],     Ud[n * 256 + k0 + 1]);
        __half2 b1 = __floats2half2_rn(Ud[n * 256 + k0 + 8], Ud[n * 256 + k0 + 9]);
        uint2 v; v.x = *(uint32_t*)&b0; v.y = *(uint32_t*)&b1;
        g_UdF2[i] = v;
        return;
    }
    i -= 16384;
    if (i < 1024) { g_bcomb[i] = bih[i] + bhh[i]; return; }
    i -= 1024;
    if (i < 512) {
        float s = 0.f;
        for (int j = 0; j < 256; ++j) s += vy[j] * Wy[j * 512 + i];
        g_weff[i] = s; return;
    }
    i -= 512;
    if (i == 0) {
        float s = 0.f;
        for (int j = 0; j < 256; ++j) s += vy[j] * Wyb[j];
        g_beff[0] = s + vyb[0];
    }
}

// ---------------- ue_tc: Ue = enc @ Ud^T via HMMA; we = enc.wt (identical to R9) ----------------
__global__ __launch_bounds__(256, 2) void ue_tc_kernel(const float* __restrict__ enc,
                                                       const float* __restrict__ wt)
{
    extern __shared__ __align__(16) __half Eh[];
    const int tid  = threadIdx.x;
    const int lane = tid & 31;
    const int w    = tid >> 5;
    const int bt0  = blockIdx.x * 128;

    for (int i = tid; i < 8192; i += 256) {
        int r = i >> 6, c4 = i & 63;
        float4 v = ((const float4*)(enc + (size_t)(bt0 + r) * 256))[c4];
        __half2 h0 = __floats2half2_rn(v.x, v.y);
        __half2 h1 = __floats2half2_rn(v.z, v.w);
        *(__half2*)&Eh[r * UE_STRIDE + c4 * 4]     = h0;
        *(__half2*)&Eh[r * UE_STRIDE + c4 * 4 + 2] = h1;
    }
    __syncthreads();

    {
        float2 wtr[4];
#pragma unroll
        for (int i = 0; i < 4; ++i)
            wtr[i] = make_float2(wt[i * 64 + lane * 2], wt[i * 64 + lane * 2 + 1]);
        for (int r = w; r < 128; r += 8) {
            float s = 0.f;
#pragma unroll
            for (int i = 0; i < 4; ++i) {
                float2 f = __half22float2(*(__half2*)&Eh[r * UE_STRIDE + i * 64 + lane * 2]);
                s = fmaf(f.x, wtr[i].x, fmaf(f.y, wtr[i].y, s));
            }
            s = wredsum(s);
            if (lane == 0) g_we[bt0 + r] = s;
        }
    }

    const int r0   = w * 16 + (lane >> 2);
    const int koff = (lane & 3) * 2;
    const int cc   = (lane & 3) * 2;
#pragma unroll
    for (int pass = 0; pass < 2; ++pass) {
        float acc[16][4];
#pragma unroll
        for (int nt = 0; nt < 16; ++nt)
#pragma unroll
            for (int q = 0; q < 4; ++q) acc[nt][q] = 0.f;

        for (int kt = 0; kt < 16; ++kt) {
            uint4 A;
            A.x = *(const uint32_t*)&Eh[r0 * UE_STRIDE + kt * 16 + koff];
            A.y = *(const uint32_t*)&Eh[(r0 + 8) * UE_STRIDE + kt * 16 + koff];
            A.z = *(const uint32_t*)&Eh[r0 * UE_STRIDE + kt * 16 + koff + 8];
            A.w = *(const uint32_t*)&Eh[(r0 + 8) * UE_STRIDE + kt * 16 + koff + 8];
#pragma unroll
            for (int nt = 0; nt < 16; ++nt) {
                uint2 B = g_UdF2[((((pass * 16 + nt) << 4) + kt) << 5) + lane];
                mma16816(acc[nt], A, B.x, B.y);
            }
        }
#pragma unroll
        for (int nt = 0; nt < 16; ++nt) {
            int ncol = ((pass * 16 + nt) << 3) + cc;
            __half2 h01 = __floats2half2_rn(acc[nt][0], acc[nt][1]);
            __half2 h23 = __floats2half2_rn(acc[nt][2], acc[nt][3]);
            *(__half2*)(g_UeH + (size_t)(bt0 + r0) * 256 + ncol)     = h01;
            *(__half2*)(g_UeH + (size_t)(bt0 + r0 + 8) * 256 + ncol) = h23;
        }
    }
}

// ---------------- persistent decoder: 147 blocks x 512 thr, G=14, gates in registers ----------------
__global__ __launch_bounds__(512, 1) void decoder_kernel(
    const float* __restrict__ enc,
    const float* __restrict__ yin,
    const float* __restrict__ Wdb, const float* __restrict__ vd,
    const float* __restrict__ wt,  const float* __restrict__ wtb,
    const float* __restrict__ Wih, float* __restrict__ out)
{
    extern __shared__ __align__(16) float sm[];
    __half* sDSh  = (__half*)(sm + OFF_SDSH);  // [16][DSS]
    __half* sX1h  = (__half*)(sm + OFF_SX1H);  // [16][256]
    float*  sCt   = sm + OFF_SCT;              // [14][256]
    float*  sL    = sm + OFF_SL;               // [14][64]
    float*  sYt   = sm + OFF_SYT;              // [16]

    const int tid  = threadIdx.x;
    const int lane = tid & 31;
    const int wid  = tid >> 5;
    const int base = blockIdx.x * G;

    // zero fp16 state buffer (16 rows incl 2 pad) + sYt
    for (int i = tid; i < 4160; i += 512) ((float*)sDSh)[i] = 0.f;
    if (tid < 16) sYt[tid] = 0.f;

    ull vd2[4];
#pragma unroll
    for (int j = 0; j < 4; ++j)
        vd2[j] = pack2(vd[lane * 8 + 2 * j], vd[lane * 8 + 2 * j + 1]);
    const float wt256 = wt[256];
    const float wtb0  = wtb[0];

    // MMA geometry
    const int qrow = lane >> 2;
    const int koff = (lane & 3) * 2;
    const int r0A  = wid * 16 + qrow;
    const float bbA0 = Wdb[r0A], bbA1 = Wdb[r0A + 8];
    const uint4* afA = g_WdF + (wid << 10) + lane;

    // MMA-E: warp wid owns units [wid*16, wid*16+16) of ALL 4 gates.
    // Tile T = gate*16 + wid -> old WhhF index: [T>>2][kt][T&3][lane]
    const uint4* afE0 = g_WhhF + ((0 * 4 + (wid >> 2)) << 11) + ((wid & 3) << 5) + lane;
    const uint4* afE1 = g_WhhF + ((1 * 4 + (wid >> 2)) << 11) + ((wid & 3) << 5) + lane;
    const uint4* afE2 = g_WhhF + ((2 * 4 + (wid >> 2)) << 11) + ((wid & 3) << 5) + lane;
    const uint4* afE3 = g_WhhF + ((3 * 4 + (wid >> 2)) << 11) + ((wid & 3) << 5) + lane;

    // pointwise constants for this lane's two units
    const int u0 = (wid << 4) + qrow, u1 = u0 + 8;
    const float biA[2] = {g_bcomb[u0],       g_bcomb[u1]};
    const float bfA[2] = {g_bcomb[256 + u0], g_bcomb[256 + u1]};
    const float bgA[2] = {g_bcomb[512 + u0], g_bcomb[512 + u1]};
    const float boA[2] = {g_bcomb[768 + u0], g_bcomb[768 + u1]};
    const float wiA[2] = {Wih[u0],       Wih[u1]};
    const float wfA[2] = {Wih[256 + u0], Wih[256 + u1]};
    const float wgA[2] = {Wih[512 + u0], Wih[512 + u1]};
    const float woA[2] = {Wih[768 + u0], Wih[768 + u1]};

    // cell state in registers: [nt(2)][q(4)] -> (unit u0/u1, batch g0/g0+1)
    float creg[8];
#pragma unroll
    for (int j = 0; j < 8; ++j) creg[j] = 0.f;

    __syncthreads();

    for (int t = 0; t < CT; ++t) {
        // ---- MMA-A: x1[256x16] = Wd[256x512] @ [d;c][512x16] ----
        {
            float c0a[4] = {0, 0, 0, 0}, c1a[4] = {0, 0, 0, 0};
            float c0b[4] = {0, 0, 0, 0}, c1b[4] = {0, 0, 0, 0};
#pragma unroll 4
            for (int kt = 0; kt < 32; kt += 2) {
                uint4 A0 = afA[kt << 5];
                uint4 A1 = afA[(kt + 1) << 5];
                int k0 = (kt << 4) + koff;
                uint32_t b00 = *(const uint32_t*)(sDSh + qrow * DSS + k0);
                uint32_t b01 = *(const uint32_t*)(sDSh + qrow * DSS + k0 + 8);
                uint32_t b10 = *(const uint32_t*)(sDSh + (8 + qrow) * DSS + k0);
                uint32_t b11 = *(const uint32_t*)(sDSh + (8 + qrow) * DSS + k0 + 8);
                int k1 = k0 + 16;
                uint32_t d00 = *(const uint32_t*)(sDSh + qrow * DSS + k1);
                uint32_t d01 = *(const uint32_t*)(sDSh + qrow * DSS + k1 + 8);
                uint32_t d10 = *(const uint32_t*)(sDSh + (8 + qrow) * DSS + k1);
                uint32_t d11 = *(const uint32_t*)(sDSh + (8 + qrow) * DSS + k1 + 8);
                mma16816(c0a, A0, b00, b01);
                mma16816(c1a, A0, b10, b11);
                mma16816(c0b, A1, d00, d01);
                mma16816(c1b, A1, d10, d11);
            }
            float c0[4], c1[4];
#pragma unroll
            for (int q = 0; q < 4; ++q) { c0[q] = c0a[q] + c0b[q]; c1[q] = c1a[q] + c1b[q]; }
            int g0 = (lane & 3) * 2;
            sX1h[g0 * 256 + r0A]           = __float2half_rn(c0[0] + bbA0);
            sX1h[(g0 + 1) * 256 + r0A]     = __float2half_rn(c0[1] + bbA0);
            sX1h[g0 * 256 + r0A + 8]       = __float2half_rn(c0[2] + bbA1);
            sX1h[(g0 + 1) * 256 + r0A + 8] = __float2half_rn(c0[3] + bbA1);
            sX1h[(g0 + 8) * 256 + r0A]           = __float2half_rn(c1[0] + bbA0);
            sX1h[(g0 + 9) * 256 + r0A]           = __float2half_rn(c1[1] + bbA0);
            sX1h[(g0 + 8) * 256 + r0A + 8]       = __float2half_rn(c1[2] + bbA1);
            sX1h[(g0 + 9) * 256 + r0A + 8]       = __float2half_rn(c1[3] + bbA1);
        }
        __syncthreads();

        // ---- Phase B: attention scores (no barrier into MMA-E) ----
        for (int p0 = wid; p0 < G * CT; p0 += 64) {
            uint4 u[4];
#pragma unroll
            for (int j = 0; j < 4; ++j) {
                int p = p0 + 16 * j;
                int b = min(base + (p >> 6), CB - 1);
                u[j] = *((const uint4*)(g_UeH + (((size_t)b * CT + (p & 63)) << 8)) + lane);
            }
            float sres[4];
#pragma unroll
            for (int j = 0; j < 4; ++j) {
                int p = p0 + 16 * j;
                uint4 x = *((const uint4*)(sX1h + ((p >> 6) << 8)) + lane);
                const __half2* uh = (const __half2*)&u[j];
                const __half2* xh = (const __half2*)&x;
                __half2 s0 = __hadd2(uh[0], xh[0]);
                __half2 s1 = __hadd2(uh[1], xh[1]);
                __half2 s2 = __hadd2(uh[2], xh[2]);
                __half2 s3 = __hadd2(uh[3], xh[3]);
                unsigned z0 = tanh_h2(*(unsigned*)&s0);
                unsigned z1 = tanh_h2(*(unsigned*)&s1);
                unsigned z2 = tanh_h2(*(unsigned*)&s2);
                unsigned z3 = tanh_h2(*(unsigned*)&s3);
                float2 f0 = __half22float2(*(__half2*)&z0);
                float2 f1 = __half22float2(*(__half2*)&z1);
                float2 f2 = __half22float2(*(__half2*)&z2);
                float2 f3 = __half22float2(*(__half2*)&z3);
                ull acc = 0ull;
                acc = fma2(pack2(f0.x, f0.y), vd2[0], acc);
                acc = fma2(pack2(f1.x, f1.y), vd2[1], acc);
                acc = fma2(pack2(f2.x, f2.y), vd2[2], acc);
                acc = fma2(pack2(f3.x, f3.y), vd2[3], acc);
                float2 f = unpack2(acc);
                sres[j] = f.x + f.y;
            }
#pragma unroll
            for (int o = 16; o; o >>= 1) {
#pragma unroll
                for (int j = 0; j < 4; ++j)
                    sres[j] += __shfl_xor_sync(0xffffffffu, sres[j], o);
            }
            if (lane == 0) {
#pragma unroll
                for (int j = 0; j < 4; ++j) sL[p0 + 16 * j] = sres[j];
            }
        }

        // ---- MMA-E: all 4 gates for units [wid*16, wid*16+16), accumulators stay in regs ----
        float cE[4][2][4];
#pragma unroll
        for (int gate = 0; gate < 4; ++gate)
#pragma unroll
            for (int nt = 0; nt < 2; ++nt)
#pragma unroll
                for (int q = 0; q < 4; ++q) cE[gate][nt][q] = 0.f;
        {
#pragma unroll 2
            for (int kt = 0; kt < 16; ++kt) {
                int k0 = (kt << 4) + koff;
                uint32_t b00 = *(const uint32_t*)(sDSh + qrow * DSS + k0);
                uint32_t b01 = *(const uint32_t*)(sDSh + qrow * DSS + k0 + 8);
                uint32_t b10 = *(const uint32_t*)(sDSh + (8 + qrow) * DSS + k0);
                uint32_t b11 = *(const uint32_t*)(sDSh + (8 + qrow) * DSS + k0 + 8);
                uint4 A0 = afE0[kt << 7];
                uint4 A1 = afE1[kt << 7];
                uint4 A2 = afE2[kt << 7];
                uint4 A3 = afE3[kt << 7];
                mma16816(cE[0][0], A0, b00, b01); mma16816(cE[0][1], A0, b10, b11);
                mma16816(cE[1][0], A1, b00, b01); mma16816(cE[1][1], A1, b10, b11);
                mma16816(cE[2][0], A2, b00, b01); mma16816(cE[2][1], A2, b10, b11);
                mma16816(cE[3][0], A3, b00, b01); mma16816(cE[3][1], A3, b10, b11);
            }
        }
        __syncthreads();

        // ---- B2: softmax + fused y_tilda (warps 0-13) ----
        if (wid < G) {
            int g = wid;
            int b = min(base + g, CB - 1);
            float l0 = sL[g * 64 + lane], l1 = sL[g * 64 + 32 + lane];
            float mx = wredmax(fmaxf(l0, l1));
            float e0 = fast_ex2((l0 - mx) * 1.4426950408889634f);
            float e1 = fast_ex2((l1 - mx) * 1.4426950408889634f);
            float w0 = g_we[b * CT + lane], w1 = g_we[b * CT + 32 + lane];
            float ps = e0 + e1;
            float pw = fmaf(e0, w0, e1 * w1);
#pragma unroll
            for (int o = 16; o; o >>= 1) {
                ps += __shfl_xor_sync(0xffffffffu, ps, o);
                pw += __shfl_xor_sync(0xffffffffu, pw, o);
            }
            float inv = fast_rcp(ps);
            inv = inv * (2.f - ps * inv);
            sL[g * 64 + lane]      = e0 * inv;
            sL[g * 64 + 32 + lane] = e1 * inv;
            if (lane == 0) {
                float yt = yin[b * CT + t];
                sYt[g] = fmaf(pw, inv, fmaf(yt, wt256, wtb0));
            }
        }
        __syncthreads();

        // ---- Pointwise: LSTM update entirely in registers ----
        {
#pragma unroll
            for (int nt = 0; nt < 2; ++nt) {
                int gb = nt * 8 + (lane & 3) * 2;
#pragma unroll
                for (int q = 0; q < 4; ++q) {
                    int ui = q >> 1;            // c0,c1 -> u0 ; c2,c3 -> u1
                    int g  = gb + (q & 1);
                    float yt = sYt[g];
                    float iv = cE[0][nt][q] + biA[ui] + yt * wiA[ui];
                    float fv = cE[1][nt][q] + bfA[ui] + yt * wfA[ui];
                    float gv = cE[2][nt][q] + bgA[ui] + yt * wgA[ui];
                    float ov = cE[3][nt][q] + boA[ui] + yt * woA[ui];
                    float cn = fmaf(sigm_f(fv), creg[nt * 4 + q], sigm_f(iv) * tanh_f(gv));
                    creg[nt * 4 + q] = cn;
                    float h = sigm_f(ov) * tanh_f(cn);
                    if (g < G) {
                        int u = ui ? u1 : u0;
                        sDSh[g * DSS + u]       = __float2half_rn(h);
                        sDSh[g * DSS + 256 + u] = __float2half_rn(cn);
                    }
                }
            }
        }
        __syncthreads();
    }

    // ---- Phase C (once): c_t = beta @ enc (fp32, exact) ----
    if (wid < G) {
        int g = wid;
        int b = min(base + g, CB - 1);
        const float4* ep = (const float4*)(enc + (size_t)b * CT * 256) + lane * 2;
        float4 a0 = make_float4(0.f, 0.f, 0.f, 0.f);
        float4 a1 = make_float4(0.f, 0.f, 0.f, 0.f);
#pragma unroll 4
        for (int tt = 0; tt < 64; ++tt) {
            float bb = sL[g * 64 + tt];
            float4 e0 = ep[tt * 64];
            float4 e1 = ep[tt * 64 + 1];
            a0.x = fmaf(bb, e0.x, a0.x); a0.y = fmaf(bb, e0.y, a0.y);
            a0.z = fmaf(bb, e0.z, a0.z); a0.w = fmaf(bb, e0.w, a0.w);
            a1.x = fmaf(bb, e1.x, a1.x); a1.y = fmaf(bb, e1.y, a1.y);
            a1.z = fmaf(bb, e1.z, a1.z); a1.w = fmaf(bb, e1.w, a1.w);
        }
        float* cp = sCt + g * 256 + lane * 8;
        ((float4*)cp)[0] = a0;
        ((float4*)cp)[1] = a1;
    }
    __syncthreads();

    // ---- Final head ----
    if (wid < G) {
        int g = wid;
        float s = 0.f;
#pragma unroll
        for (int i = 0; i < 8; ++i) {
            int m = lane + 32 * i;
            s = fmaf(__half2float(sDSh[g * DSS + m]), g_weff[m], s);
            s = fmaf(sCt[g * 256 + m], g_weff[256 + m], s);
        }
        s = wredsum(s);
        if (lane == 0 && base + g < CB) out[base + g] = s + g_beff[0];
    }
    for (int p = tid; p < G * CT; p += 512) {
        int g = p >> 6, tt = p & 63;
        if (base + g < CB)
            out[CB + (size_t)(base + g) * CT + tt] = sL[g * 64 + tt];
    }
}

// ---------------- launcher ----------------
extern "C" void kernel_launch(void* const* d_in, const int* in_sizes, int n_in,
                              void* d_out, int out_size)
{
    (void)in_sizes; (void)n_in; (void)out_size;
    const float* enc = (const float*)d_in[0];
    const float* y   = (const float*)d_in[1];
    const float* Wd  = (const float*)d_in[2];
    const float* Wdb = (const float*)d_in[3];
    const float* Ud  = (const float*)d_in[4];
    const float* vd  = (const float*)d_in[5];
    const float* wt  = (const float*)d_in[6];
    const float* wtb = (const float*)d_in[7];
    const float* Wy  = (const float*)d_in[8];
    const float* Wyb = (const float*)d_in[9];
    const float* vy  = (const float*)d_in[10];
    const float* vyb = (const float*)d_in[11];
    const float* Wih = (const float*)d_in[12];
    const float* Whh = (const float*)d_in[13];
    const float* bih = (const float*)d_in[14];
    const float* bhh = (const float*)d_in[15];
    float* out = (float*)d_out;

    cudaFuncSetAttribute(decoder_kernel,
                         cudaFuncAttributeMaxDynamicSharedMemorySize, SMEM_BYTES);
    cudaFuncSetAttribute(ue_tc_kernel,
                         cudaFuncAttributeMaxDynamicSharedMemorySize, UE_SMEM_BYTES);

    prep_kernel<<<263, 256>>>(Wd, Whh, Ud, bih, bhh, vy, Wy, Wyb, vyb);
    ue_tc_kernel<<<1024, 256, UE_SMEM_BYTES>>>(enc, wt);
    decoder_kernel<<<NBLK, 512, SMEM_BYTES>>>(enc, y, Wdb, vd, wt, wtb, Wih, out);
}

// round 16
// speedup vs baseline: 1.8368x; 1.0658x over previous
#include <cuda_runtime.h>
#include <cuda_fp16.h>
#include <cstdint>

// Problem constants
#define CB   2048
#define CT   64
#define CM   256
#define CP   256
#define G    14      // batches per block
#define GP   20      // padded batch stride (floats)
#define NBLK 147
#define DSS  520     // sDSh row stride in halves ([d(256) | c(256)] + pad)

// decoder smem layout (float offsets)
#define OFF_SGATE 0        // [1024][GP] fp32 gates        = 20480
#define OFF_SD    20480    // [256][GP] fp32 hidden d      = 5120
#define OFF_SS    25600    // [256][GP] fp32 cell c        = 5120
#define OFF_SDSH  30720    // [16][DSS] fp16 [d|c]         = 4160 floats
#define OFF_SX1H  34880    // [16][256] fp16 x1            = 2048 floats
#define OFF_SCT   36928    // [14][256] fp32 context       = 3584
#define OFF_SL    40512    // [14][64] scores/beta         = 896
#define OFF_SYT   41408    // [16] y_tilda
#define SMEM_FLOATS 41424
#define SMEM_BYTES  (SMEM_FLOATS * 4)

// ue_tc smem: [128][280] halves
#define UE_STRIDE 280
#define UE_SMEM_BYTES (128 * UE_STRIDE * 2)

typedef unsigned long long ull;

// ---------------- device scratch ----------------
__device__ __align__(16) __half  g_UeH[(size_t)CB * CT * CM];   // fp16 Ue
__device__ __align__(16) float   g_we[(size_t)CB * CT];         // enc . w_tilda
__device__ __align__(16) uint4   g_WdF[16 * 32 * 32];           // Wd  fragments [w][kt][lane]
__device__ __align__(16) uint4   g_WhhF[16 * 16 * 4 * 32];      // Whh fragments [w][kt][mt][lane]
__device__ __align__(16) uint2   g_UdF2[32 * 16 * 32];          // Ud  B-fragments [nt][kt][lane]
__device__ float g_bcomb[1024];
__device__ float g_weff[512];
__device__ float g_beff[1];

// ---------------- helpers ----------------
__device__ __forceinline__ ull pack2(float lo, float hi) {
    ull r; asm("mov.b64 %0, {%1, %2};" : "=l"(r) : "f"(lo), "f"(hi)); return r;
}
__device__ __forceinline__ ull bcast2(float x) { return pack2(x, x); }
__device__ __forceinline__ ull fma2(ull a, ull b, ull c) {
    ull d; asm("fma.rn.f32x2 %0, %1, %2, %3;" : "=l"(d) : "l"(a), "l"(b), "l"(c)); return d;
}
__device__ __forceinline__ float2 unpack2(ull v) {
    float2 f; asm("mov.b64 {%0, %1}, %2;" : "=f"(f.x), "=f"(f.y) : "l"(v)); return f;
}
__device__ __forceinline__ float fast_ex2(float x) {
    float y; asm("ex2.approx.f32 %0, %1;" : "=f"(y) : "f"(x)); return y;
}
__device__ __forceinline__ float fast_rcp(float x) {
    float y; asm("rcp.approx.f32 %0, %1;" : "=f"(y) : "f"(x)); return y;
}
__device__ __forceinline__ float tanh_f(float x) {
    float e = fast_ex2(2.8853900817779268f * x);
    return fmaf(-2.f, fast_rcp(e + 1.f), 1.f);
}
__device__ __forceinline__ unsigned tanh_h2(unsigned x) {
    unsigned y; asm("tanh.approx.f16x2 %0, %1;" : "=r"(y) : "r"(x)); return y;
}
__device__ __forceinline__ float sigm_f(float x) {
    float e = fast_ex2(-1.4426950408889634f * x);
    return fast_rcp(1.f + e);
}
__device__ __forceinline__ float wredsum(float s) {
#pragma unroll
    for (int o = 16; o; o >>= 1) s += __shfl_xor_sync(0xffffffffu, s, o);
    return s;
}
__device__ __forceinline__ float wredmax(float s) {
#pragma unroll
    for (int o = 16; o; o >>= 1) s = fmaxf(s, __shfl_xor_sync(0xffffffffu, s, o));
    return s;
}
// m16n8k16 row.col f32.f16.f16.f32
__device__ __forceinline__ void mma16816(float* c, uint4 A, uint32_t b0, uint32_t b1) {
    asm volatile("mma.sync.aligned.m16n8k16.row.col.f32.f16.f16.f32 "
        "{%0,%1,%2,%3}, {%4,%5,%6,%7}, {%8,%9}, {%0,%1,%2,%3};"
        : "+f"(c[0]), "+f"(c[1]), "+f"(c[2]), "+f"(c[3])
        : "r"(A.x), "r"(A.y), "r"(A.z), "r"(A.w), "r"(b0), "r"(b1));
}

// ---------------- prep: weight fragments + folded head ----------------
__global__ void prep_kernel(const float* __restrict__ Wd,
                            const float* __restrict__ Whh,
                            const float* __restrict__ Ud,
                            const float* __restrict__ bih,
                            const float* __restrict__ bhh,
                            const float* __restrict__ vy,
                            const float* __restrict__ Wy,
                            const float* __restrict__ Wyb,
                            const float* __restrict__ vyb)
{
    int i = blockIdx.x * blockDim.x + threadIdx.x;
    if (i < 16384) {   // Wd fragments: [w(16)][kt(32)][lane(32)]
        int lane = i & 31, kt = (i >> 5) & 31, w = i >> 10;
        int j0 = w * 16 + (lane >> 2);
        int k0 = kt * 16 + (lane & 3) * 2;
        __half2 a = __floats2half2_rn(Wd[j0 * 512 + k0],       Wd[j0 * 512 + k0 + 1]);
        __half2 b = __floats2half2_rn(Wd[(j0 + 8) * 512 + k0], Wd[(j0 + 8) * 512 + k0 + 1]);
        __half2 c = __floats2half2_rn(Wd[j0 * 512 + k0 + 8],   Wd[j0 * 512 + k0 + 9]);
        __half2 d = __floats2half2_rn(Wd[(j0 + 8) * 512 + k0 + 8], Wd[(j0 + 8) * 512 + k0 + 9]);
        uint4 v;
        v.x = *(uint32_t*)&a; v.y = *(uint32_t*)&b; v.z = *(uint32_t*)&c; v.w = *(uint32_t*)&d;
        g_WdF[i] = v;
        return;
    }
    i -= 16384;
    if (i < 32768) {   // Whh fragments: [w(16)][kt(16)][mt(4)][lane(32)]
        int lane = i & 31, mt = (i >> 5) & 3, kt = (i >> 7) & 15, w = i >> 11;
        int j0 = w * 64 + mt * 16 + (lane >> 2);
        int k0 = kt * 16 + (lane & 3) * 2;
        __half2 a = __floats2half2_rn(Whh[j0 * 256 + k0],       Whh[j0 * 256 + k0 + 1]);
        __half2 b = __floats2half2_rn(Whh[(j0 + 8) * 256 + k0], Whh[(j0 + 8) * 256 + k0 + 1]);
        __half2 c = __floats2half2_rn(Whh[j0 * 256 + k0 + 8],   Whh[j0 * 256 + k0 + 9]);
        __half2 d = __floats2half2_rn(Whh[(j0 + 8) * 256 + k0 + 8], Whh[(j0 + 8) * 256 + k0 + 9]);
        uint4 v;
        v.x = *(uint32_t*)&a; v.y = *(uint32_t*)&b; v.z = *(uint32_t*)&c; v.w = *(uint32_t*)&d;
        g_WhhF[i] = v;
        return;
    }
    i -= 32768;
    if (i < 16384) {   // Ud B-fragments: [nt(32)][kt(16)][lane(32)]
        int lane = i & 31, kt = (i >> 5) & 15, nt = i >> 9;
        int n = nt * 8 + (lane >> 2);
        int k0 = kt * 16 + (lane & 3) * 2;
        __half2 b0 = __floats2half2_rn(Ud[n * 256 + k0],     Ud[n * 256 + k0 + 1]);
        __half2 b1 = __floats2half2_rn(Ud[n * 256 + k0 + 8], Ud[n * 256 + k0 + 9]);
        uint2 v; v.x = *(uint32_t*)&b0; v.y = *(uint32_t*)&b1;
        g_UdF2[i] = v;
        return;
    }
    i -= 16384;
    if (i < 1024) { g_bcomb[i] = bih[i] + bhh[i]; return; }
    i -= 1024;
    if (i < 512) {
        float s = 0.f;
        for (int j = 0; j < 256; ++j) s += vy[j] * Wy[j * 512 + i];
        g_weff[i] = s; return;
    }
    i -= 512;
    if (i == 0) {
        float s = 0.f;
        for (int j = 0; j < 256; ++j) s += vy[j] * Wyb[j];
        g_beff[0] = s + vyb[0];
    }
}

// ---------------- ue_tc: Ue = enc @ Ud^T via HMMA; we = enc.wt ----------------
__global__ __launch_bounds__(256, 2) void ue_tc_kernel(const float* __restrict__ enc,
                                                       const float* __restrict__ wt)
{
    extern __shared__ __align__(16) __half Eh[];
    const int tid  = threadIdx.x;
    const int lane = tid & 31;
    const int w    = tid >> 5;
    const int bt0  = blockIdx.x * 128;

    for (int i = tid; i < 8192; i += 256) {
        int r = i >> 6, c4 = i & 63;
        float4 v = ((const float4*)(enc + (size_t)(bt0 + r) * 256))[c4];
        __half2 h0 = __floats2half2_rn(v.x, v.y);
        __half2 h1 = __floats2half2_rn(v.z, v.w);
        *(__half2*)&Eh[r * UE_STRIDE + c4 * 4]     = h0;
        *(__half2*)&Eh[r * UE_STRIDE + c4 * 4 + 2] = h1;
    }
    __syncthreads();

    {
        float2 wtr[4];
#pragma unroll
        for (int i = 0; i < 4; ++i)
            wtr[i] = make_float2(wt[i * 64 + lane * 2], wt[i * 64 + lane * 2 + 1]);
        for (int r = w; r < 128; r += 8) {
            float s = 0.f;
#pragma unroll
            for (int i = 0; i < 4; ++i) {
                float2 f = __half22float2(*(__half2*)&Eh[r * UE_STRIDE + i * 64 + lane * 2]);
                s = fmaf(f.x, wtr[i].x, fmaf(f.y, wtr[i].y, s));
            }
            s = wredsum(s);
            if (lane == 0) g_we[bt0 + r] = s;
        }
    }

    const int r0   = w * 16 + (lane >> 2);
    const int koff = (lane & 3) * 2;
    const int cc   = (lane & 3) * 2;
#pragma unroll
    for (int pass = 0; pass < 2; ++pass) {
        float acc[16][4];
#pragma unroll
        for (int nt = 0; nt < 16; ++nt)
#pragma unroll
            for (int q = 0; q < 4; ++q) acc[nt][q] = 0.f;

        for (int kt = 0; kt < 16; ++kt) {
            uint4 A;
            A.x = *(const uint32_t*)&Eh[r0 * UE_STRIDE + kt * 16 + koff];
            A.y = *(const uint32_t*)&Eh[(r0 + 8) * UE_STRIDE + kt * 16 + koff];
            A.z = *(const uint32_t*)&Eh[r0 * UE_STRIDE + kt * 16 + koff + 8];
            A.w = *(const uint32_t*)&Eh[(r0 + 8) * UE_STRIDE + kt * 16 + koff + 8];
#pragma unroll
            for (int nt = 0; nt < 16; ++nt) {
                uint2 B = g_UdF2[((((pass * 16 + nt) << 4) + kt) << 5) + lane];
                mma16816(acc[nt], A, B.x, B.y);
            }
        }
#pragma unroll
        for (int nt = 0; nt < 16; ++nt) {
            int ncol = ((pass * 16 + nt) << 3) + cc;
            __half2 h01 = __floats2half2_rn(acc[nt][0], acc[nt][1]);
            __half2 h23 = __floats2half2_rn(acc[nt][2], acc[nt][3]);
            *(__half2*)(g_UeH + (size_t)(bt0 + r0) * 256 + ncol)     = h01;
            *(__half2*)(g_UeH + (size_t)(bt0 + r0 + 8) * 256 + ncol) = h23;
        }
    }
}

// ---------------- persistent decoder: 147 blocks x 512 thr, G=14 ----------------
__global__ __launch_bounds__(512, 1) void decoder_kernel(
    const float* __restrict__ enc,
    const float* __restrict__ yin,
    const float* __restrict__ Wdb, const float* __restrict__ vd,
    const float* __restrict__ wt,  const float* __restrict__ wtb,
    const float* __restrict__ Wih, float* __restrict__ out)
{
    extern __shared__ __align__(16) float sm[];
    float*  sGate = sm + OFF_SGATE;
    float*  sD    = sm + OFF_SD;
    float*  sS    = sm + OFF_SS;
    __half* sDSh  = (__half*)(sm + OFF_SDSH);
    __half* sX1h  = (__half*)(sm + OFF_SX1H);
    float*  sCt   = sm + OFF_SCT;
    float*  sL    = sm + OFF_SL;
    float*  sYt   = sm + OFF_SYT;

    const int tid  = threadIdx.x;
    const int lane = tid & 31;
    const int wid  = tid >> 5;
    const int half = tid >> 8;
    const int n    = tid & 255;
    const int base = blockIdx.x * G;

    for (int i = tid; i < 10240; i += 512) sD[i] = 0.f;    // covers sD & sS
    for (int i = tid; i < 4160; i += 512) ((float*)sDSh)[i] = 0.f;
    if (tid < 16) sYt[tid] = 0.f;

    // vd packed as half2 (fp16 dot accumulation in Phase B)
    __half2 vdh[4];
#pragma unroll
    for (int j = 0; j < 4; ++j)
        vdh[j] = __floats2half2_rn(vd[lane * 8 + 2 * j], vd[lane * 8 + 2 * j + 1]);
    const float wt256 = wt[256];
    const float wtb0  = wtb[0];

    const float bI = g_bcomb[n],       wI = Wih[n];
    const float bF = g_bcomb[256 + n], wF = Wih[256 + n];
    const float bG = g_bcomb[512 + n], wG = Wih[512 + n];
    const float bO = g_bcomb[768 + n], wO = Wih[768 + n];

    const int n0   = lane >> 2;
    const int koff = (lane & 3) * 2;
    const int r0A  = wid * 16 + n0;
    const float bb0 = Wdb[r0A], bb1 = Wdb[r0A + 8];
    const uint4* afA = g_WdF  + (wid << 10) + lane;
    const uint4* afE = g_WhhF + (wid << 11) + lane;
    const bool b_first = ((wid >> 2) & 1) == 0;   // 2 B-first + 2 E-first warps per SMSP

    __syncthreads();

    for (int t = 0; t < CT; ++t) {
        // ---- MMA-A: split accumulators (4 chains of 16) ----
        {
            float c0a[4] = {0, 0, 0, 0}, c1a[4] = {0, 0, 0, 0};
            float c0b[4] = {0, 0, 0, 0}, c1b[4] = {0, 0, 0, 0};
#pragma unroll 4
            for (int kt = 0; kt < 32; kt += 2) {
                uint4 A0 = afA[kt << 5];
                uint4 A1 = afA[(kt + 1) << 5];
                int k0 = (kt << 4) + koff;
                uint32_t b00 = *(const uint32_t*)(sDSh + n0 * DSS + k0);
                uint32_t b01 = *(const uint32_t*)(sDSh + n0 * DSS + k0 + 8);
                uint32_t b10 = *(const uint32_t*)(sDSh + (8 + n0) * DSS + k0);
                uint32_t b11 = *(const uint32_t*)(sDSh + (8 + n0) * DSS + k0 + 8);
                int k1 = k0 + 16;
                uint32_t d00 = *(const uint32_t*)(sDSh + n0 * DSS + k1);
                uint32_t d01 = *(const uint32_t*)(sDSh + n0 * DSS + k1 + 8);
                uint32_t d10 = *(const uint32_t*)(sDSh + (8 + n0) * DSS + k1);
                uint32_t d11 = *(const uint32_t*)(sDSh + (8 + n0) * DSS + k1 + 8);
                mma16816(c0a, A0, b00, b01);
                mma16816(c1a, A0, b10, b11);
                mma16816(c0b, A1, d00, d01);
                mma16816(c1b, A1, d10, d11);
            }
            float c0[4], c1[4];
#pragma unroll
            for (int q = 0; q < 4; ++q) { c0[q] = c0a[q] + c0b[q]; c1[q] = c1a[q] + c1b[q]; }
            int g0 = (lane & 3) * 2;
            sX1h[g0 * 256 + r0A]           = __float2half_rn(c0[0] + bb0);
            sX1h[(g0 + 1) * 256 + r0A]     = __float2half_rn(c0[1] + bb0);
            sX1h[g0 * 256 + r0A + 8]       = __float2half_rn(c0[2] + bb1);
            sX1h[(g0 + 1) * 256 + r0A + 8] = __float2half_rn(c0[3] + bb1);
            sX1h[(g0 + 8) * 256 + r0A]           = __float2half_rn(c1[0] + bb0);
            sX1h[(g0 + 9) * 256 + r0A]           = __float2half_rn(c1[1] + bb0);
            sX1h[(g0 + 8) * 256 + r0A + 8]       = __float2half_rn(c1[2] + bb1);
            sX1h[(g0 + 9) * 256 + r0A + 8]       = __float2half_rn(c1[3] + bb1);
        }
        __syncthreads();

        // ---- Phase B (fp16 dot) and MMA-E, anti-correlated order across warps ----
        auto phaseB = [&]() {
            for (int p0 = wid; p0 < G * CT; p0 += 64) {
                uint4 u[4];
#pragma unroll
                for (int j = 0; j < 4; ++j) {
                    int p = p0 + 16 * j;
                    int b = min(base + (p >> 6), CB - 1);
                    u[j] = *((const uint4*)(g_UeH + (((size_t)b * CT + (p & 63)) << 8)) + lane);
                }
                float sres[4];
#pragma unroll
                for (int j = 0; j < 4; ++j) {
                    int p = p0 + 16 * j;
                    uint4 x = *((const uint4*)(sX1h + ((p >> 6) << 8)) + lane);
                    const __half2* uh = (const __half2*)&u[j];
                    const __half2* xh = (const __half2*)&x;
                    __half2 s0 = __hadd2(uh[0], xh[0]);
                    __half2 s1 = __hadd2(uh[1], xh[1]);
                    __half2 s2 = __hadd2(uh[2], xh[2]);
                    __half2 s3 = __hadd2(uh[3], xh[3]);
                    unsigned z0 = tanh_h2(*(unsigned*)&s0);
                    unsigned z1 = tanh_h2(*(unsigned*)&s1);
                    unsigned z2 = tanh_h2(*(unsigned*)&s2);
                    unsigned z3 = tanh_h2(*(unsigned*)&s3);
                    __half2 acc = __floats2half2_rn(0.f, 0.f);
                    acc = __hfma2(*(__half2*)&z0, vdh[0], acc);
                    acc = __hfma2(*(__half2*)&z1, vdh[1], acc);
                    acc = __hfma2(*(__half2*)&z2, vdh[2], acc);
                    acc = __hfma2(*(__half2*)&z3, vdh[3], acc);
                    float2 f = __half22float2(acc);
                    sres[j] = f.x + f.y;
                }
#pragma unroll
                for (int o = 16; o; o >>= 1) {
#pragma unroll
                    for (int j = 0; j < 4; ++j)
                        sres[j] += __shfl_xor_sync(0xffffffffu, sres[j], o);
                }
                if (lane == 0) {
#pragma unroll
                    for (int j = 0; j < 4; ++j) sL[p0 + 16 * j] = sres[j];
                }
            }
        };
        auto phaseE = [&]() {
            float c[4][2][4];
#pragma unroll
            for (int mt = 0; mt < 4; ++mt)
#pragma unroll
                for (int nt = 0; nt < 2; ++nt)
#pragma unroll
                    for (int q = 0; q < 4; ++q) c[mt][nt][q] = 0.f;
#pragma unroll 2
            for (int kt = 0; kt < 16; ++kt) {
                int k0 = (kt << 4) + koff;
                uint32_t b00 = *(const uint32_t*)(sDSh + n0 * DSS + k0);
                uint32_t b01 = *(const uint32_t*)(sDSh + n0 * DSS + k0 + 8);
                uint32_t b10 = *(const uint32_t*)(sDSh + (8 + n0) * DSS + k0);
                uint32_t b11 = *(const uint32_t*)(sDSh + (8 + n0) * DSS + k0 + 8);
#pragma unroll
                for (int mt = 0; mt < 4; ++mt) {
                    uint4 A = afE[((kt << 2) + mt) << 5];
                    mma16816(c[mt][0], A, b00, b01);
                    mma16816(c[mt][1], A, b10, b11);
                }
            }
            int g0 = (lane & 3) * 2;
#pragma unroll
            for (int mt = 0; mt < 4; ++mt) {
                int r = wid * 64 + mt * 16 + n0;
#pragma unroll
                for (int nt = 0; nt < 2; ++nt) {
                    int g = nt * 8 + g0;
                    *(float2*)&sGate[r * GP + g]       = make_float2(c[mt][nt][0], c[mt][nt][1]);
                    *(float2*)&sGate[(r + 8) * GP + g] = make_float2(c[mt][nt][2], c[mt][nt][3]);
                }
            }
        };
        if (b_first) { phaseB(); phaseE(); }
        else         { phaseE(); phaseB(); }
        __syncthreads();

        // ---- B2: softmax + fused y_tilda ----
        if (wid < G) {
            int g = wid;
            int b = min(base + g, CB - 1);
            float l0 = sL[g * 64 + lane], l1 = sL[g * 64 + 32 + lane];
            float mx = wredmax(fmaxf(l0, l1));
            float e0 = fast_ex2((l0 - mx) * 1.4426950408889634f);
            float e1 = fast_ex2((l1 - mx) * 1.4426950408889634f);
            float w0 = g_we[b * CT + lane], w1 = g_we[b * CT + 32 + lane];
            float ps = e0 + e1;
            float pw = fmaf(e0, w0, e1 * w1);
#pragma unroll
            for (int o = 16; o; o >>= 1) {
                ps += __shfl_xor_sync(0xffffffffu, ps, o);
                pw += __shfl_xor_sync(0xffffffffu, pw, o);
            }
            float inv = fast_rcp(ps);
            inv = inv * (2.f - ps * inv);
            sL[g * 64 + lane]      = e0 * inv;
            sL[g * 64 + 32 + lane] = e1 * inv;
            if (lane == 0) {
                float yt = yin[b * CT + t];
                sYt[g] = fmaf(pw, inv, fmaf(yt, wt256, wtb0));
            }
        }
        __syncthreads();

        // ---- E-final: LSTM pointwise ----
        {
#pragma unroll
            for (int gi = 0; gi < 7; ++gi) {
                int g = half * 7 + gi;
                float yt = sYt[g];
                float iv = sGate[n * GP + g]         + bI + yt * wI;
                float fv = sGate[(256 + n) * GP + g] + bF + yt * wF;
                float gv = sGate[(512 + n) * GP + g] + bG + yt * wG;
                float ov = sGate[(768 + n) * GP + g] + bO + yt * wO;
                float c_old = sS[n * GP + g];
                float cn = fmaf(sigm_f(fv), c_old, sigm_f(iv) * tanh_f(gv));
                sS[n * GP + g] = cn;
                float h = sigm_f(ov) * tanh_f(cn);
                sD[n * GP + g] = h;
                sDSh[g * DSS + n]       = __float2half_rn(h);
                sDSh[g * DSS + 256 + n] = __float2half_rn(cn);
            }
        }
        __syncthreads();
    }

    // ---- Phase C (once): c_t = beta @ enc (fp32, exact) ----
    if (wid < G) {
        int g = wid;
        int b = min(base + g, CB - 1);
        const float4* ep = (const float4*)(enc + (size_t)b * CT * 256) + lane * 2;
        float4 a0 = make_float4(0.f, 0.f, 0.f, 0.f);
        float4 a1 = make_float4(0.f, 0.f, 0.f, 0.f);
#pragma unroll 4
        for (int tt = 0; tt < 64; ++tt) {
            float bb = sL[g * 64 + tt];
            float4 e0 = ep[tt * 64];
            float4 e1 = ep[tt * 64 + 1];
            a0.x = fmaf(bb, e0.x, a0.x); a0.y = fmaf(bb, e0.y, a0.y);
            a0.z = fmaf(bb, e0.z, a0.z); a0.w = fmaf(bb, e0.w, a0.w);
            a1.x = fmaf(bb, e1.x, a1.x); a1.y = fmaf(bb, e1.y, a1.y);
            a1.z = fmaf(bb, e1.z, a1.z); a1.w = fmaf(bb, e1.w, a1.w);
        }
        float* cp = sCt + g * 256 + lane * 8;
        ((float4*)cp)[0] = a0;
        ((float4*)cp)[1] = a1;
    }
    __syncthreads();

    // ---- Final head ----
    if (wid < G) {
        int g = wid;
        float s = 0.f;
#pragma unroll
        for (int i = 0; i < 8; ++i) {
            int m = lane + 32 * i;
            s = fmaf(sD[m * GP + g], g_weff[m], s);
            s = fmaf(sCt[g * 256 + m], g_weff[256 + m], s);
        }
        s = wredsum(s);
        if (lane == 0 && base + g < CB) out[base + g] = s + g_beff[0];
    }
    for (int p = tid; p < G * CT; p += 512) {
        int g = p >> 6, tt = p & 63;
        if (base + g < CB)
            out[CB + (size_t)(base + g) * CT + tt] = sL[g * 64 + tt];
    }
}

// ---------------- launcher ----------------
extern "C" void kernel_launch(void* const* d_in, const int* in_sizes, int n_in,
                              void* d_out, int out_size)
{
    (void)in_sizes; (void)n_in; (void)out_size;
    const float* enc = (const float*)d_in[0];
    const float* y   = (const float*)d_in[1];
    const float* Wd  = (const float*)d_in[2];
    const float* Wdb = (const float*)d_in[3];
    const float* Ud  = (const float*)d_in[4];
    const float* vd  = (const float*)d_in[5];
    const float* wt  = (const float*)d_in[6];
    const float* wtb = (const float*)d_in[7];
    const float* Wy  = (const float*)d_in[8];
    const float* Wyb = (const float*)d_in[9];
    const float* vy  = (const float*)d_in[10];
    const float* vyb = (const float*)d_in[11];
    const float* Wih = (const float*)d_in[12];
    const float* Whh = (const float*)d_in[13];
    const float* bih = (const float*)d_in[14];
    const float* bhh = (const float*)d_in[15];
    float* out = (float*)d_out;

    cudaFuncSetAttribute(decoder_kernel,
                         cudaFuncAttributeMaxDynamicSharedMemorySize, SMEM_BYTES);
    cudaFuncSetAttribute(ue_tc_kernel,
                         cudaFuncAttributeMaxDynamicSharedMemorySize, UE_SMEM_BYTES);

    prep_kernel<<<263, 256>>>(Wd, Whh, Ud, bih, bhh, vy, Wy, Wyb, vyb);
    ue_tc_kernel<<<1024, 256, UE_SMEM_BYTES>>>(enc, wt);
    decoder_kernel<<<NBLK, 512, SMEM_BYTES>>>(enc, y, Wdb, vd, wt, wtb, Wih, out);
}

// round 17
// speedup vs baseline: 1.8625x; 1.0140x over previous
#include <cuda_runtime.h>
#include <cuda_fp16.h>
#include <cstdint>

// Problem constants
#define CB   2048
#define CT   64
#define CM   256
#define CP   256
#define G    14      // batches per block
#define GP   20      // padded batch stride (floats)
#define NBLK 147
#define DSS  520     // sDSh row stride in halves ([d(256) | c(256)] + pad)

// decoder smem layout (float offsets)
#define OFF_SGATE 0        // [1024][GP] fp32 gates        = 20480
#define OFF_SDSH  20480    // [16][DSS] fp16 [d|c]         = 4160 floats
#define OFF_SX1H  24640    // [16][256] fp16 x1            = 2048 floats
#define OFF_SCT   26688    // [14][256] fp32 context       = 3584
#define OFF_SL    30272    // [14][64] scores/beta         = 896
#define OFF_SYT   31168    // [16] y_tilda
#define SMEM_FLOATS 31184
#define SMEM_BYTES  (SMEM_FLOATS * 4)   // 124,736 B

// ue_tc smem: [128][280] halves
#define UE_STRIDE 280
#define UE_SMEM_BYTES (128 * UE_STRIDE * 2)

typedef unsigned long long ull;

// ---------------- device scratch ----------------
__device__ __align__(16) __half  g_UeH[(size_t)CB * CT * CM];   // fp16 Ue
__device__ __align__(16) float   g_we[(size_t)CB * CT];         // enc . w_tilda
__device__ __align__(16) uint4   g_WdF[16 * 32 * 32];           // Wd  fragments [w][kt][lane]
__device__ __align__(16) uint4   g_WhhF[16 * 16 * 4 * 32];      // Whh fragments [w][kt][mt][lane]
__device__ __align__(16) uint2   g_UdF2[32 * 16 * 32];          // Ud  B-fragments [nt][kt][lane]
__device__ float g_bcomb[1024];
__device__ float g_weff[512];
__device__ float g_beff[1];

// ---------------- helpers ----------------
__device__ __forceinline__ ull pack2(float lo, float hi) {
    ull r; asm("mov.b64 %0, {%1, %2};" : "=l"(r) : "f"(lo), "f"(hi)); return r;
}
__device__ __forceinline__ ull bcast2(float x) { return pack2(x, x); }
__device__ __forceinline__ ull fma2(ull a, ull b, ull c) {
    ull d; asm("fma.rn.f32x2 %0, %1, %2, %3;" : "=l"(d) : "l"(a), "l"(b), "l"(c)); return d;
}
__device__ __forceinline__ float2 unpack2(ull v) {
    float2 f; asm("mov.b64 {%0, %1}, %2;" : "=f"(f.x), "=f"(f.y) : "l"(v)); return f;
}
__device__ __forceinline__ float fast_ex2(float x) {
    float y; asm("ex2.approx.f32 %0, %1;" : "=f"(y) : "f"(x)); return y;
}
__device__ __forceinline__ float fast_rcp(float x) {
    float y; asm("rcp.approx.f32 %0, %1;" : "=f"(y) : "f"(x)); return y;
}
__device__ __forceinline__ float tanh_f(float x) {
    float e = fast_ex2(2.8853900817779268f * x);
    return fmaf(-2.f, fast_rcp(e + 1.f), 1.f);
}
__device__ __forceinline__ unsigned tanh_h2(unsigned x) {
    unsigned y; asm("tanh.approx.f16x2 %0, %1;" : "=r"(y) : "r"(x)); return y;
}
__device__ __forceinline__ float sigm_f(float x) {
    float e = fast_ex2(-1.4426950408889634f * x);
    return fast_rcp(1.f + e);
}
__device__ __forceinline__ float wredsum(float s) {
#pragma unroll
    for (int o = 16; o; o >>= 1) s += __shfl_xor_sync(0xffffffffu, s, o);
    return s;
}
__device__ __forceinline__ float wredmax(float s) {
#pragma unroll
    for (int o = 16; o; o >>= 1) s = fmaxf(s, __shfl_xor_sync(0xffffffffu, s, o));
    return s;
}
// m16n8k16 row.col f32.f16.f16.f32
__device__ __forceinline__ void mma16816(float* c, uint4 A, uint32_t b0, uint32_t b1) {
    asm volatile("mma.sync.aligned.m16n8k16.row.col.f32.f16.f16.f32 "
        "{%0,%1,%2,%3}, {%4,%5,%6,%7}, {%8,%9}, {%0,%1,%2,%3};"
        : "+f"(c[0]), "+f"(c[1]), "+f"(c[2]), "+f"(c[3])
        : "r"(A.x), "r"(A.y), "r"(A.z), "r"(A.w), "r"(b0), "r"(b1));
}
// m16n8k16 row.col f16.f16.f16.f16 (fp16 accumulate; 2-reg D/C)
__device__ __forceinline__ void mma16816h(uint32_t* c, uint4 A, uint32_t b0, uint32_t b1) {
    asm volatile("mma.sync.aligned.m16n8k16.row.col.f16.f16.f16.f16 "
        "{%0,%1}, {%2,%3,%4,%5}, {%6,%7}, {%0,%1};"
        : "+r"(c[0]), "+r"(c[1])
        : "r"(A.x), "r"(A.y), "r"(A.z), "r"(A.w), "r"(b0), "r"(b1));
}

// ---------------- prep: weight fragments + folded head ----------------
__global__ void prep_kernel(const float* __restrict__ Wd,
                            const float* __restrict__ Whh,
                            const float* __restrict__ Ud,
                            const float* __restrict__ bih,
                            const float* __restrict__ bhh,
                            const float* __restrict__ vy,
                            const float* __restrict__ Wy,
                            const float* __restrict__ Wyb,
                            const float* __restrict__ vyb)
{
    int i = blockIdx.x * blockDim.x + threadIdx.x;
    if (i < 16384) {   // Wd fragments: [w(16)][kt(32)][lane(32)]
        int lane = i & 31, kt = (i >> 5) & 31, w = i >> 10;
        int j0 = w * 16 + (lane >> 2);
        int k0 = kt * 16 + (lane & 3) * 2;
        __half2 a = __floats2half2_rn(Wd[j0 * 512 + k0],       Wd[j0 * 512 + k0 + 1]);
        __half2 b = __floats2half2_rn(Wd[(j0 + 8) * 512 + k0], Wd[(j0 + 8) * 512 + k0 + 1]);
        __half2 c = __floats2half2_rn(Wd[j0 * 512 + k0 + 8],   Wd[j0 * 512 + k0 + 9]);
        __half2 d = __floats2half2_rn(Wd[(j0 + 8) * 512 + k0 + 8], Wd[(j0 + 8) * 512 + k0 + 9]);
        uint4 v;
        v.x = *(uint32_t*)&a; v.y = *(uint32_t*)&b; v.z = *(uint32_t*)&c; v.w = *(uint32_t*)&d;
        g_WdF[i] = v;
        return;
    }
    i -= 16384;
    if (i < 32768) {   // Whh fragments: [w(16)][kt(16)][mt(4)][lane(32)]
        int lane = i & 31, mt = (i >> 5) & 3, kt = (i >> 7) & 15, w = i >> 11;
        int j0 = w * 64 + mt * 16 + (lane >> 2);
        int k0 = kt * 16 + (lane & 3) * 2;
        __half2 a = __floats2half2_rn(Whh[j0 * 256 + k0],       Whh[j0 * 256 + k0 + 1]);
        __half2 b = __floats2half2_rn(Whh[(j0 + 8) * 256 + k0], Whh[(j0 + 8) * 256 + k0 + 1]);
        __half2 c = __floats2half2_rn(Whh[j0 * 256 + k0 + 8],   Whh[j0 * 256 + k0 + 9]);
        __half2 d = __floats2half2_rn(Whh[(j0 + 8) * 256 + k0 + 8], Whh[(j0 + 8) * 256 + k0 + 9]);
        uint4 v;
        v.x = *(uint32_t*)&a; v.y = *(uint32_t*)&b; v.z = *(uint32_t*)&c; v.w = *(uint32_t*)&d;
        g_WhhF[i] = v;
        return;
    }
    i -= 32768;
    if (i < 16384) {   // Ud B-fragments: [nt(32)][kt(16)][lane(32)]
        int lane = i & 31, kt = (i >> 5) & 15, nt = i >> 9;
        int n = nt * 8 + (lane >> 2);
        int k0 = kt * 16 + (lane & 3) * 2;
        __half2 b0 = __floats2half2_rn(Ud[n * 256 + k0],     Ud[n * 256 + k0 + 1]);
        __half2 b1 = __floats2half2_rn(Ud[n * 256 + k0 + 8], Ud[n * 256 + k0 + 9]);
        uint2 v; v.x = *(uint32_t*)&b0; v.y = *(uint32_t*)&b1;
        g_UdF2[i] = v;
        return;
    }
    i -= 16384;
    if (i < 1024) { g_bcomb[i] = bih[i] + bhh[i]; return; }
    i -= 1024;
    if (i < 512) {
        float s = 0.f;
        for (int j = 0; j < 256; ++j) s += vy[j] * Wy[j * 512 + i];
        g_weff[i] = s; return;
    }
    i -= 512;
    if (i == 0) {
        float s = 0.f;
        for (int j = 0; j < 256; ++j) s += vy[j] * Wyb[j];
        g_beff[0] = s + vyb[0];
    }
}

// ---------------- ue_tc: Ue = enc @ Ud^T via HMMA; we = enc.wt ----------------
__global__ __launch_bounds__(256, 2) void ue_tc_kernel(const float* __restrict__ enc,
                                                       const float* __restrict__ wt)
{
    extern __shared__ __align__(16) __half Eh[];
    const int tid  = threadIdx.x;
    const int lane = tid & 31;
    const int w    = tid >> 5;
    const int bt0  = blockIdx.x * 128;

    for (int i = tid; i < 8192; i += 256) {
        int r = i >> 6, c4 = i & 63;
        float4 v = ((const float4*)(enc + (size_t)(bt0 + r) * 256))[c4];
        __half2 h0 = __floats2half2_rn(v.x, v.y);
        __half2 h1 = __floats2half2_rn(v.z, v.w);
        *(__half2*)&Eh[r * UE_STRIDE + c4 * 4]     = h0;
        *(__half2*)&Eh[r * UE_STRIDE + c4 * 4 + 2] = h1;
    }
    __syncthreads();

    {
        float2 wtr[4];
#pragma unroll
        for (int i = 0; i < 4; ++i)
            wtr[i] = make_float2(wt[i * 64 + lane * 2], wt[i * 64 + lane * 2 + 1]);
        for (int r = w; r < 128; r += 8) {
            float s = 0.f;
#pragma unroll
            for (int i = 0; i < 4; ++i) {
                float2 f = __half22float2(*(__half2*)&Eh[r * UE_STRIDE + i * 64 + lane * 2]);
                s = fmaf(f.x, wtr[i].x, fmaf(f.y, wtr[i].y, s));
            }
            s = wredsum(s);
            if (lane == 0) g_we[bt0 + r] = s;
        }
    }

    const int r0   = w * 16 + (lane >> 2);
    const int koff = (lane & 3) * 2;
    const int cc   = (lane & 3) * 2;
#pragma unroll
    for (int pass = 0; pass < 2; ++pass) {
        float acc[16][4];
#pragma unroll
        for (int nt = 0; nt < 16; ++nt)
#pragma unroll
            for (int q = 0; q < 4; ++q) acc[nt][q] = 0.f;

        for (int kt = 0; kt < 16; ++kt) {
            uint4 A;
            A.x = *(const uint32_t*)&Eh[r0 * UE_STRIDE + kt * 16 + koff];
            A.y = *(const uint32_t*)&Eh[(r0 + 8) * UE_STRIDE + kt * 16 + koff];
            A.z = *(const uint32_t*)&Eh[r0 * UE_STRIDE + kt * 16 + koff + 8];
            A.w = *(const uint32_t*)&Eh[(r0 + 8) * UE_STRIDE + kt * 16 + koff + 8];
#pragma unroll
            for (int nt = 0; nt < 16; ++nt) {
                uint2 B = g_UdF2[((((pass * 16 + nt) << 4) + kt) << 5) + lane];
                mma16816(acc[nt], A, B.x, B.y);
            }
        }
#pragma unroll
        for (int nt = 0; nt < 16; ++nt) {
            int ncol = ((pass * 16 + nt) << 3) + cc;
            __half2 h01 = __floats2half2_rn(acc[nt][0], acc[nt][1]);
            __half2 h23 = __floats2half2_rn(acc[nt][2], acc[nt][3]);
            *(__half2*)(g_UeH + (size_t)(bt0 + r0) * 256 + ncol)     = h01;
            *(__half2*)(g_UeH + (size_t)(bt0 + r0 + 8) * 256 + ncol) = h23;
        }
    }
}

// ---------------- persistent decoder: 147 blocks x 512 thr, G=14 ----------------
__global__ __launch_bounds__(512, 1) void decoder_kernel(
    const float* __restrict__ enc,
    const float* __restrict__ yin,
    const float* __restrict__ Wdb, const float* __restrict__ vd,
    const float* __restrict__ wt,  const float* __restrict__ wtb,
    const float* __restrict__ Wih, float* __restrict__ out)
{
    extern __shared__ __align__(16) float sm[];
    float*  sGate = sm + OFF_SGATE;
    __half* sDSh  = (__half*)(sm + OFF_SDSH);
    __half* sX1h  = (__half*)(sm + OFF_SX1H);
    float*  sCt   = sm + OFF_SCT;
    float*  sL    = sm + OFF_SL;
    float*  sYt   = sm + OFF_SYT;

    const int tid  = threadIdx.x;
    const int lane = tid & 31;
    const int wid  = tid >> 5;
    const int half = tid >> 8;
    const int n    = tid & 255;
    const int base = blockIdx.x * G;

    for (int i = tid; i < 4160; i += 512) ((float*)sDSh)[i] = 0.f;
    if (tid < 16) sYt[tid] = 0.f;

    // vd packed as half2 (fp16 dot accumulation in Phase B)
    __half2 vdh[4];
#pragma unroll
    for (int j = 0; j < 4; ++j)
        vdh[j] = __floats2half2_rn(vd[lane * 8 + 2 * j], vd[lane * 8 + 2 * j + 1]);
    const float wt256 = wt[256];
    const float wtb0  = wtb[0];

    const float bI = g_bcomb[n],       wI = Wih[n];
    const float bF = g_bcomb[256 + n], wF = Wih[256 + n];
    const float bG = g_bcomb[512 + n], wG = Wih[512 + n];
    const float bO = g_bcomb[768 + n], wO = Wih[768 + n];
    float creg[7];   // cell state in registers (batches half*7 + 0..6)
#pragma unroll
    for (int j = 0; j < 7; ++j) creg[j] = 0.f;

    const int n0   = lane >> 2;
    const int koff = (lane & 3) * 2;
    const int r0A  = wid * 16 + n0;
    const __half2 bb0h = __half2half2(__float2half_rn(Wdb[r0A]));
    const __half2 bb1h = __half2half2(__float2half_rn(Wdb[r0A + 8]));
    const uint4* afA = g_WdF  + (wid << 10) + lane;
    const uint4* afE = g_WhhF + (wid << 11) + lane;
    const bool b_first = ((wid >> 2) & 1) == 0;   // 2 B-first + 2 E-first warps per SMSP

    __syncthreads();

    for (int t = 0; t < CT; ++t) {
        // ---- MMA-A: fp16 accumulate (4 chains of 16, 2 regs each) ----
        {
            uint32_t c0a[2] = {0, 0}, c1a[2] = {0, 0};
            uint32_t c0b[2] = {0, 0}, c1b[2] = {0, 0};
#pragma unroll 4
            for (int kt = 0; kt < 32; kt += 2) {
                uint4 A0 = afA[kt << 5];
                uint4 A1 = afA[(kt + 1) << 5];
                int k0 = (kt << 4) + koff;
                uint32_t b00 = *(const uint32_t*)(sDSh + n0 * DSS + k0);
                uint32_t b01 = *(const uint32_t*)(sDSh + n0 * DSS + k0 + 8);
                uint32_t b10 = *(const uint32_t*)(sDSh + (8 + n0) * DSS + k0);
                uint32_t b11 = *(const uint32_t*)(sDSh + (8 + n0) * DSS + k0 + 8);
                int k1 = k0 + 16;
                uint32_t d00 = *(const uint32_t*)(sDSh + n0 * DSS + k1);
                uint32_t d01 = *(const uint32_t*)(sDSh + n0 * DSS + k1 + 8);
                uint32_t d10 = *(const uint32_t*)(sDSh + (8 + n0) * DSS + k1);
                uint32_t d11 = *(const uint32_t*)(sDSh + (8 + n0) * DSS + k1 + 8);
                mma16816h(c0a, A0, b00, b01);
                mma16816h(c1a, A0, b10, b11);
                mma16816h(c0b, A1, d00, d01);
                mma16816h(c1b, A1, d10, d11);
            }
            // combine + bias (half2), scatter to sX1h
            __half2 s00 = __hadd2(__hadd2(*(__half2*)&c0a[0], *(__half2*)&c0b[0]), bb0h);
            __half2 s01 = __hadd2(__hadd2(*(__half2*)&c0a[1], *(__half2*)&c0b[1]), bb1h);
            __half2 s10 = __hadd2(__hadd2(*(__half2*)&c1a[0], *(__half2*)&c1b[0]), bb0h);
            __half2 s11 = __hadd2(__hadd2(*(__half2*)&c1a[1], *(__half2*)&c1b[1]), bb1h);
            int g0 = (lane & 3) * 2;
            sX1h[g0 * 256 + r0A]           = __low2half(s00);
            sX1h[(g0 + 1) * 256 + r0A]     = __high2half(s00);
            sX1h[g0 * 256 + r0A + 8]       = __low2half(s01);
            sX1h[(g0 + 1) * 256 + r0A + 8] = __high2half(s01);
            sX1h[(g0 + 8) * 256 + r0A]           = __low2half(s10);
            sX1h[(g0 + 9) * 256 + r0A]           = __high2half(s10);
            sX1h[(g0 + 8) * 256 + r0A + 8]       = __low2half(s11);
            sX1h[(g0 + 9) * 256 + r0A + 8]       = __high2half(s11);
        }
        __syncthreads();

        // ---- Phase B (fp16 dot) and MMA-E, anti-correlated order across warps ----
        auto phaseB = [&]() {
            for (int p0 = wid; p0 < G * CT; p0 += 64) {
                uint4 u[4];
#pragma unroll
                for (int j = 0; j < 4; ++j) {
                    int p = p0 + 16 * j;
                    int b = min(base + (p >> 6), CB - 1);
                    u[j] = *((const uint4*)(g_UeH + (((size_t)b * CT + (p & 63)) << 8)) + lane);
                }
                float sres[4];
#pragma unroll
                for (int j = 0; j < 4; ++j) {
                    int p = p0 + 16 * j;
                    uint4 x = *((const uint4*)(sX1h + ((p >> 6) << 8)) + lane);
                    const __half2* uh = (const __half2*)&u[j];
                    const __half2* xh = (const __half2*)&x;
                    __half2 s0 = __hadd2(uh[0], xh[0]);
                    __half2 s1 = __hadd2(uh[1], xh[1]);
                    __half2 s2 = __hadd2(uh[2], xh[2]);
                    __half2 s3 = __hadd2(uh[3], xh[3]);
                    unsigned z0 = tanh_h2(*(unsigned*)&s0);
                    unsigned z1 = tanh_h2(*(unsigned*)&s1);
                    unsigned z2 = tanh_h2(*(unsigned*)&s2);
                    unsigned z3 = tanh_h2(*(unsigned*)&s3);
                    __half2 acc = __floats2half2_rn(0.f, 0.f);
                    acc = __hfma2(*(__half2*)&z0, vdh[0], acc);
                    acc = __hfma2(*(__half2*)&z1, vdh[1], acc);
                    acc = __hfma2(*(__half2*)&z2, vdh[2], acc);
                    acc = __hfma2(*(__half2*)&z3, vdh[3], acc);
                    float2 f = __half22float2(acc);
                    sres[j] = f.x + f.y;
                }
#pragma unroll
                for (int o = 16; o; o >>= 1) {
#pragma unroll
                    for (int j = 0; j < 4; ++j)
                        sres[j] += __shfl_xor_sync(0xffffffffu, sres[j], o);
                }
                if (lane == 0) {
#pragma unroll
                    for (int j = 0; j < 4; ++j) sL[p0 + 16 * j] = sres[j];
                }
            }
        };
        auto phaseE = [&]() {
            float c[4][2][4];
#pragma unroll
            for (int mt = 0; mt < 4; ++mt)
#pragma unroll
                for (int nt = 0; nt < 2; ++nt)
#pragma unroll
                    for (int q = 0; q < 4; ++q) c[mt][nt][q] = 0.f;
#pragma unroll 2
            for (int kt = 0; kt < 16; ++kt) {
                int k0 = (kt << 4) + koff;
                uint32_t b00 = *(const uint32_t*)(sDSh + n0 * DSS + k0);
                uint32_t b01 = *(const uint32_t*)(sDSh + n0 * DSS + k0 + 8);
                uint32_t b10 = *(const uint32_t*)(sDSh + (8 + n0) * DSS + k0);
                uint32_t b11 = *(const uint32_t*)(sDSh + (8 + n0) * DSS + k0 + 8);
#pragma unroll
                for (int mt = 0; mt < 4; ++mt) {
                    uint4 A = afE[((kt << 2) + mt) << 5];
                    mma16816(c[mt][0], A, b00, b01);
                    mma16816(c[mt][1], A, b10, b11);
                }
            }
            int g0 = (lane & 3) * 2;
#pragma unroll
            for (int mt = 0; mt < 4; ++mt) {
                int r = wid * 64 + mt * 16 + n0;
#pragma unroll
                for (int nt = 0; nt < 2; ++nt) {
                    int g = nt * 8 + g0;
                    *(float2*)&sGate[r * GP + g]       = make_float2(c[mt][nt][0], c[mt][nt][1]);
                    *(float2*)&sGate[(r + 8) * GP + g] = make_float2(c[mt][nt][2], c[mt][nt][3]);
                }
            }
        };
        if (b_first) { phaseB(); phaseE(); }
        else         { phaseE(); phaseB(); }
        __syncthreads();

        // ---- B2: softmax + fused y_tilda ----
        if (wid < G) {
            int g = wid;
            int b = min(base + g, CB - 1);
            float l0 = sL[g * 64 + lane], l1 = sL[g * 64 + 32 + lane];
            float mx = wredmax(fmaxf(l0, l1));
            float e0 = fast_ex2((l0 - mx) * 1.4426950408889634f);
            float e1 = fast_ex2((l1 - mx) * 1.4426950408889634f);
            float w0 = g_we[b * CT + lane], w1 = g_we[b * CT + 32 + lane];
            float ps = e0 + e1;
            float pw = fmaf(e0, w0, e1 * w1);
#pragma unroll
            for (int o = 16; o; o >>= 1) {
                ps += __shfl_xor_sync(0xffffffffu, ps, o);
                pw += __shfl_xor_sync(0xffffffffu, pw, o);
            }
            float inv = fast_rcp(ps);
            inv = inv * (2.f - ps * inv);
            sL[g * 64 + lane]      = e0 * inv;
            sL[g * 64 + 32 + lane] = e1 * inv;
            if (lane == 0) {
                float yt = yin[b * CT + t];
                sYt[g] = fmaf(pw, inv, fmaf(yt, wt256, wtb0));
            }
        }
        __syncthreads();

        // ---- E-final: LSTM pointwise (cell state in registers) ----
        {
#pragma unroll
            for (int gi = 0; gi < 7; ++gi) {
                int g = half * 7 + gi;
                float yt = sYt[g];
                float iv = sGate[n * GP + g]         + bI + yt * wI;
                float fv = sGate[(256 + n) * GP + g] + bF + yt * wF;
                float gv = sGate[(512 + n) * GP + g] + bG + yt * wG;
                float ov = sGate[(768 + n) * GP + g] + bO + yt * wO;
                float cn = fmaf(sigm_f(fv), creg[gi], sigm_f(iv) * tanh_f(gv));
                creg[gi] = cn;
                float h = sigm_f(ov) * tanh_f(cn);
                sDSh[g * DSS + n]       = __float2half_rn(h);
                sDSh[g * DSS + 256 + n] = __float2half_rn(cn);
            }
        }
        __syncthreads();
    }

    // ---- Phase C (once): c_t = beta @ enc (fp32, exact) ----
    if (wid < G) {
        int g = wid;
        int b = min(base + g, CB - 1);
        const float4* ep = (const float4*)(enc + (size_t)b * CT * 256) + lane * 2;
        float4 a0 = make_float4(0.f, 0.f, 0.f, 0.f);
        float4 a1 = make_float4(0.f, 0.f, 0.f, 0.f);
#pragma unroll 4
        for (int tt = 0; tt < 64; ++tt) {
            float bb = sL[g * 64 + tt];
            float4 e0 = ep[tt * 64];
            float4 e1 = ep[tt * 64 + 1];
            a0.x = fmaf(bb, e0.x, a0.x); a0.y = fmaf(bb, e0.y, a0.y);
            a0.z = fmaf(bb, e0.z, a0.z); a0.w = fmaf(bb, e0.w, a0.w);
            a1.x = fmaf(bb, e1.x, a1.x); a1.y = fmaf(bb, e1.y, a1.y);
            a1.z = fmaf(bb, e1.z, a1.z); a1.w = fmaf(bb, e1.w, a1.w);
        }
        float* cp = sCt + g * 256 + lane * 8;
        ((float4*)cp)[0] = a0;
        ((float4*)cp)[1] = a1;
    }
    __syncthreads();

    // ---- Final head (d from fp16 state buffer) ----
    if (wid < G) {
        int g = wid;
        float s = 0.f;
#pragma unroll
        for (int i = 0; i < 8; ++i) {
            int m = lane + 32 * i;
            s = fmaf(__half2float(sDSh[g * DSS + m]), g_weff[m], s);
            s = fmaf(sCt[g * 256 + m], g_weff[256 + m], s);
        }
        s = wredsum(s);
        if (lane == 0 && base + g < CB) out[base + g] = s + g_beff[0];
    }
    for (int p = tid; p < G * CT; p += 512) {
        int g = p >> 6, tt = p & 63;
        if (base + g < CB)
            out[CB + (size_t)(base + g) * CT + tt] = sL[g * 64 + tt];
    }
}

// ---------------- launcher ----------------
extern "C" void kernel_launch(void* const* d_in, const int* in_sizes, int n_in,
                              void* d_out, int out_size)
{
    (void)in_sizes; (void)n_in; (void)out_size;
    const float* enc = (const float*)d_in[0];
    const float* y   = (const float*)d_in[1];
    const float* Wd  = (const float*)d_in[2];
    const float* Wdb = (const float*)d_in[3];
    const float* Ud  = (const float*)d_in[4];
    const float* vd  = (const float*)d_in[5];
    const float* wt  = (const float*)d_in[6];
    const float* wtb = (const float*)d_in[7];
    const float* Wy  = (const float*)d_in[8];
    const float* Wyb = (const float*)d_in[9];
    const float* vy  = (const float*)d_in[10];
    const float* vyb = (const float*)d_in[11];
    const float* Wih = (const float*)d_in[12];
    const float* Whh = (const float*)d_in[13];
    const float* bih = (const float*)d_in[14];
    const float* bhh = (const float*)d_in[15];
    float* out = (float*)d_out;

    cudaFuncSetAttribute(decoder_kernel,
                         cudaFuncAttributeMaxDynamicSharedMemorySize, SMEM_BYTES);
    cudaFuncSetAttribute(ue_tc_kernel,
                         cudaFuncAttributeMaxDynamicSharedMemorySize, UE_SMEM_BYTES);

    prep_kernel<<<263, 256>>>(Wd, Whh, Ud, bih, bhh, vy, Wy, Wyb, vyb);
    ue_tc_kernel<<<1024, 256, UE_SMEM_BYTES>>>(enc, wt);
    decoder_kernel<<<NBLK, 512, SMEM_BYTES>>>(enc, y, Wdb, vd, wt, wtb, Wih, out);
}